// round 2
// baseline (speedup 1.0000x reference)
#include <cuda_runtime.h>
#include <stdint.h>

// Problem dims (fixed by the dataset)
#define M_TOTAL 8192   // B*S = 4*2048
#define E_DIM   1024   // embedding
#define P_DIM   4096   // number of P-tokens (keys)

// 128 MB scratch for the score / attention matrix [M_TOTAL, P_DIM].
// __device__ globals are the sanctioned scratch mechanism (no cudaMalloc allowed).
__device__ float g_scores[(size_t)M_TOTAL * (size_t)P_DIM];

// ---------------------------------------------------------------------------
// TF32 helpers (mma.sync.aligned.m16n8k8.row.col.f32.tf32.tf32.f32)
// Fragment layouts (per PTX ISA):
//   A (16x8, row-major): a0=(grp,tig) a1=(grp+8,tig) a2=(grp,tig+4) a3=(grp+8,tig+4)
//   B (8x8,  col-major): b0=(k=tig, n=grp) b1=(k=tig+4, n=grp)
//   C (16x8): c0=(grp,2*tig) c1=(grp,2*tig+1) c2=(grp+8,2*tig) c3=(grp+8,2*tig+1)
// where grp = lane>>2, tig = lane&3.
// ---------------------------------------------------------------------------
__device__ __forceinline__ uint32_t f2tf32(float x) {
    uint32_t r;
    asm("cvt.rna.tf32.f32 %0, %1;" : "=r"(r) : "f"(x));
    return r;
}

__device__ __forceinline__ void mma_tf32(float c[4], const uint32_t a[4], const uint32_t b[2]) {
    asm volatile(
        "mma.sync.aligned.m16n8k8.row.col.f32.tf32.tf32.f32 "
        "{%0,%1,%2,%3}, {%4,%5,%6,%7}, {%8,%9}, {%0,%1,%2,%3};"
        : "+f"(c[0]), "+f"(c[1]), "+f"(c[2]), "+f"(c[3])
        : "r"(a[0]), "r"(a[1]), "r"(a[2]), "r"(a[3]),
          "r"(b[0]), "r"(b[1]));
}

// ---------------------------------------------------------------------------
// Kernel 1: S[m, p] = (1/sqrt(E)) * sum_e X[m,e] * K[p,e]
// CTA tile 128(M) x 128(P), k-chunk 32 over E. 256 threads = 8 warps (2x4),
// warp tile 64x32. Both X and K are row-major with E contiguous -> "row.col"
// mma maps directly (B fragment gathers K[n, k]).
// ---------------------------------------------------------------------------
__global__ __launch_bounds__(256) void qk_gemm(const float* __restrict__ X,
                                               const float* __restrict__ Kw) {
    // stride 36 floats: 144B rows (16B aligned for float4 stores) and
    // conflict-free fragment reads (bank = (4*grp + tig) covers 0..31).
    __shared__ float As[128][36];
    __shared__ float Bs[128][36];

    const int tid  = threadIdx.x;
    const int lane = tid & 31;
    const int wid  = tid >> 5;
    const int wm   = (wid >> 2) * 64;   // warp M offset within CTA tile
    const int wn   = (wid & 3) * 32;    // warp N offset within CTA tile
    const int bm   = blockIdx.y * 128;
    const int bn   = blockIdx.x * 128;
    const int tig  = lane & 3;
    const int grp  = lane >> 2;

    float acc[4][4][4];
    #pragma unroll
    for (int mi = 0; mi < 4; mi++)
        #pragma unroll
        for (int ni = 0; ni < 4; ni++)
            #pragma unroll
            for (int c = 0; c < 4; c++)
                acc[mi][ni][c] = 0.0f;

    for (int k0 = 0; k0 < E_DIM; k0 += 32) {
        // Load A tile (X rows bm..bm+127, cols k0..k0+31) and B tile (K rows
        // bn..bn+127, cols k0..k0+31). 1024 float4 each, 4 per thread.
        #pragma unroll
        for (int i = 0; i < 4; i++) {
            int lin = tid + 256 * i;
            int r   = lin >> 3;
            int c4  = (lin & 7) * 4;
            float4 va = *(const float4*)(X  + (size_t)(bm + r) * E_DIM + k0 + c4);
            As[r][c4 + 0] = va.x; As[r][c4 + 1] = va.y;
            As[r][c4 + 2] = va.z; As[r][c4 + 3] = va.w;
            float4 vb = *(const float4*)(Kw + (size_t)(bn + r) * E_DIM + k0 + c4);
            Bs[r][c4 + 0] = vb.x; Bs[r][c4 + 1] = vb.y;
            Bs[r][c4 + 2] = vb.z; Bs[r][c4 + 3] = vb.w;
        }
        __syncthreads();

        #pragma unroll
        for (int kk = 0; kk < 4; kk++) {
            const int kc = kk * 8 + tig;
            uint32_t a[4][4];
            #pragma unroll
            for (int mi = 0; mi < 4; mi++) {
                const int ar = wm + mi * 16;
                a[mi][0] = f2tf32(As[ar + grp    ][kc    ]);
                a[mi][1] = f2tf32(As[ar + grp + 8][kc    ]);
                a[mi][2] = f2tf32(As[ar + grp    ][kc + 4]);
                a[mi][3] = f2tf32(As[ar + grp + 8][kc + 4]);
            }
            uint32_t b[4][2];
            #pragma unroll
            for (int ni = 0; ni < 4; ni++) {
                const int bc = wn + ni * 8 + grp;   // n index (row of K)
                b[ni][0] = f2tf32(Bs[bc][kc    ]);
                b[ni][1] = f2tf32(Bs[bc][kc + 4]);
            }
            #pragma unroll
            for (int mi = 0; mi < 4; mi++)
                #pragma unroll
                for (int ni = 0; ni < 4; ni++)
                    mma_tf32(acc[mi][ni], a[mi], b[ni]);
        }
        __syncthreads();
    }

    // Epilogue: scale by 1/sqrt(1024) = 1/32, store to scratch.
    const float scale = 0.03125f;
    #pragma unroll
    for (int mi = 0; mi < 4; mi++) {
        #pragma unroll
        for (int ni = 0; ni < 4; ni++) {
            const int r = bm + wm + mi * 16 + grp;
            const int c = bn + wn + ni * 8 + 2 * tig;
            float2 v0 = make_float2(acc[mi][ni][0] * scale, acc[mi][ni][1] * scale);
            float2 v1 = make_float2(acc[mi][ni][2] * scale, acc[mi][ni][3] * scale);
            *(float2*)&g_scores[(size_t)r       * P_DIM + c] = v0;
            *(float2*)&g_scores[(size_t)(r + 8) * P_DIM + c] = v1;
        }
    }
}

// ---------------------------------------------------------------------------
// Kernel 2: in-place row softmax over P_DIM=4096. One CTA (256 threads) per
// row; each thread holds 16 values in registers (one read + one write of the
// 128 MB scratch). Keeps all EX2 work out of the GEMM inner loops.
// ---------------------------------------------------------------------------
__global__ __launch_bounds__(256) void softmax_rows() {
    __shared__ float red[8];
    const int row  = blockIdx.x;
    const int t    = threadIdx.x;
    const int lane = t & 31;
    const int w    = t >> 5;
    float* sr = g_scores + (size_t)row * P_DIM;

    float v[16];
    float m = -3.0e38f;
    #pragma unroll
    for (int i = 0; i < 16; i++) {
        v[i] = sr[t + 256 * i];
        m = fmaxf(m, v[i]);
    }
    #pragma unroll
    for (int o = 16; o > 0; o >>= 1)
        m = fmaxf(m, __shfl_xor_sync(0xffffffffu, m, o));
    if (lane == 0) red[w] = m;
    __syncthreads();
    m = red[0];
    #pragma unroll
    for (int i = 1; i < 8; i++) m = fmaxf(m, red[i]);

    float e[16];
    float s = 0.0f;
    #pragma unroll
    for (int i = 0; i < 16; i++) {
        e[i] = __expf(v[i] - m);
        s += e[i];
    }
    #pragma unroll
    for (int o = 16; o > 0; o >>= 1)
        s += __shfl_xor_sync(0xffffffffu, s, o);
    __syncthreads();               // red[] reuse
    if (lane == 0) red[w] = s;
    __syncthreads();
    s = 0.0f;
    #pragma unroll
    for (int i = 0; i < 8; i++) s += red[i];
    const float inv = 1.0f / s;

    #pragma unroll
    for (int i = 0; i < 16; i++)
        sr[t + 256 * i] = e[i] * inv;
}

// ---------------------------------------------------------------------------
// Kernel 3: out[m, e] = sum_p A[m, p] * V[p, e].
// Same skeleton; B tile is now [k][n] (V rows are the reduction dim, E is
// contiguous). Bs2 stride 136 floats -> 16B-aligned rows and conflict-free
// fragment reads (bank = 8*tig + grp covers 0..31).
// ---------------------------------------------------------------------------
__global__ __launch_bounds__(256) void av_gemm(const float* __restrict__ V,
                                               float* __restrict__ out) {
    __shared__ float As[128][36];
    __shared__ float Bs2[32][136];

    const int tid  = threadIdx.x;
    const int lane = tid & 31;
    const int wid  = tid >> 5;
    const int wm   = (wid >> 2) * 64;
    const int wn   = (wid & 3) * 32;
    const int bm   = blockIdx.y * 128;
    const int bn   = blockIdx.x * 128;   // over E
    const int tig  = lane & 3;
    const int grp  = lane >> 2;

    float acc[4][4][4];
    #pragma unroll
    for (int mi = 0; mi < 4; mi++)
        #pragma unroll
        for (int ni = 0; ni < 4; ni++)
            #pragma unroll
            for (int c = 0; c < 4; c++)
                acc[mi][ni][c] = 0.0f;

    for (int k0 = 0; k0 < P_DIM; k0 += 32) {
        // A tile: attn rows bm..bm+127, cols k0..k0+31
        #pragma unroll
        for (int i = 0; i < 4; i++) {
            int lin = tid + 256 * i;
            int r   = lin >> 3;
            int c4  = (lin & 7) * 4;
            float4 va = *(const float4*)(g_scores + (size_t)(bm + r) * P_DIM + k0 + c4);
            As[r][c4 + 0] = va.x; As[r][c4 + 1] = va.y;
            As[r][c4 + 2] = va.z; As[r][c4 + 3] = va.w;
        }
        // B tile: V rows k0..k0+31, cols bn..bn+127
        #pragma unroll
        for (int i = 0; i < 4; i++) {
            int lin = tid + 256 * i;
            int r   = lin >> 5;
            int c4  = (lin & 31) * 4;
            float4 vb = *(const float4*)(V + (size_t)(k0 + r) * E_DIM + bn + c4);
            Bs2[r][c4 + 0] = vb.x; Bs2[r][c4 + 1] = vb.y;
            Bs2[r][c4 + 2] = vb.z; Bs2[r][c4 + 3] = vb.w;
        }
        __syncthreads();

        #pragma unroll
        for (int kk = 0; kk < 4; kk++) {
            const int kc = kk * 8 + tig;
            uint32_t a[4][4];
            #pragma unroll
            for (int mi = 0; mi < 4; mi++) {
                const int ar = wm + mi * 16;
                a[mi][0] = f2tf32(As[ar + grp    ][kc    ]);
                a[mi][1] = f2tf32(As[ar + grp + 8][kc    ]);
                a[mi][2] = f2tf32(As[ar + grp    ][kc + 4]);
                a[mi][3] = f2tf32(As[ar + grp + 8][kc + 4]);
            }
            uint32_t b[4][2];
            #pragma unroll
            for (int ni = 0; ni < 4; ni++) {
                const int nc = wn + ni * 8 + grp;
                b[ni][0] = f2tf32(Bs2[kc    ][nc]);
                b[ni][1] = f2tf32(Bs2[kc + 4][nc]);
            }
            #pragma unroll
            for (int mi = 0; mi < 4; mi++)
                #pragma unroll
                for (int ni = 0; ni < 4; ni++)
                    mma_tf32(acc[mi][ni], a[mi], b[ni]);
        }
        __syncthreads();
    }

    #pragma unroll
    for (int mi = 0; mi < 4; mi++) {
        #pragma unroll
        for (int ni = 0; ni < 4; ni++) {
            const int r = bm + wm + mi * 16 + grp;
            const int c = bn + wn + ni * 8 + 2 * tig;
            float2 v0 = make_float2(acc[mi][ni][0], acc[mi][ni][1]);
            float2 v1 = make_float2(acc[mi][ni][2], acc[mi][ni][3]);
            *(float2*)&out[(size_t)r       * E_DIM + c] = v0;
            *(float2*)&out[(size_t)(r + 8) * E_DIM + c] = v1;
        }
    }
}

// ---------------------------------------------------------------------------
// Launch: inputs per metadata order: x [4,2048,1024], K [4096,1024], V [4096,1024].
// Output: float [4,2048,1024]. All launches on the default stream; no syncs,
// no allocations -> graph-capturable.
// ---------------------------------------------------------------------------
extern "C" void kernel_launch(void* const* d_in, const int* in_sizes, int n_in,
                              void* d_out, int out_size) {
    (void)in_sizes; (void)n_in; (void)out_size;
    const float* x  = (const float*)d_in[0];
    const float* Kw = (const float*)d_in[1];
    const float* V  = (const float*)d_in[2];
    float* out = (float*)d_out;

    qk_gemm<<<dim3(P_DIM / 128, M_TOTAL / 128), 256>>>(x, Kw);
    softmax_rows<<<M_TOTAL, 256>>>();
    av_gemm<<<dim3(E_DIM / 128, M_TOTAL / 128), 256>>>(V, out);
}

// round 5
// speedup vs baseline: 1.4068x; 1.4068x over previous
#include <cuda_runtime.h>
#include <stdint.h>

// ---------------------------------------------------------------------------
// Problem dims (fixed by the dataset)
// ---------------------------------------------------------------------------
#define M_TOTAL 8192   // B*S = 4*2048
#define E_DIM   1024
#define P_DIM   4096

// Device scratch (sanctioned mechanism: __device__ globals)
__device__ float g_scores[(size_t)M_TOTAL * (size_t)P_DIM];  // 128 MB
__device__ float g_vt[(size_t)E_DIM * (size_t)P_DIM];        // 16 MB, V^T

// ---------------------------------------------------------------------------
// TF32 helpers (legacy mma.sync path — the only tensor path at .target sm_103)
// ---------------------------------------------------------------------------
__device__ __forceinline__ uint32_t f2tf32(float x) {
    uint32_t r;
    asm("cvt.rna.tf32.f32 %0, %1;" : "=r"(r) : "f"(x));
    return r;
}

__device__ __forceinline__ void mma_tf32(float c[4], const uint32_t a[4], const uint32_t b[2]) {
    asm volatile(
        "mma.sync.aligned.m16n8k8.row.col.f32.tf32.tf32.f32 "
        "{%0,%1,%2,%3}, {%4,%5,%6,%7}, {%8,%9}, {%0,%1,%2,%3};"
        : "+f"(c[0]), "+f"(c[1]), "+f"(c[2]), "+f"(c[3])
        : "r"(a[0]), "r"(a[1]), "r"(a[2]), "r"(a[3]),
          "r"(b[0]), "r"(b[1]));
}

// ---------------------------------------------------------------------------
// GEMM: D[m,n] = sum_k A[m,k] * B[n,k]   (both K-major fp32; tf32-converted
// once at smem-store time).
// CTA 128x128, KC=32, 256 threads = 8 warps (2x4), warp tile 64x32.
//
// SMEM: stride 32 words (no pad), XOR swizzle on 4-word groups:
//   word(r, c) stored at r*32 + ((c>>2) ^ (r&7))*4 + (c&3)
// -> STS.128 conflict-free (quarter-warp banks 4*((lane&7)^const) distinct)
// -> LDS.32 fragment reads conflict-free (banks 4*((2kk+h)^grp)+tig cover 0..31)
//
// Double-buffered smem + register staging: LDG(k+1) issued before MMA(k).
// Layout: A buf0 [0,4096) A buf1 [4096,8192) B buf0 [8192,12288) B buf1 [12288,16384)
// ---------------------------------------------------------------------------
#define BM 128
#define BN 128
#define KC 32
#define SMEM_BYTES 65536

__global__ __launch_bounds__(256, 1) void gemm_tc(const float* __restrict__ Ag,
                                                  const float* __restrict__ Bg,
                                                  float* __restrict__ Dg,
                                                  int nk, int lda, int ldb, int ldd) {
    extern __shared__ uint32_t sm[];
    const int tid  = threadIdx.x;
    const int lane = tid & 31;
    const int wid  = tid >> 5;
    const int wm   = (wid >> 2) * 64;
    const int wn   = (wid & 3) * 32;
    const int bm   = blockIdx.y * BM;
    const int bn   = blockIdx.x * BN;
    const int tig  = lane & 3;
    const int grp  = lane >> 2;

    float acc[4][4][4];
    #pragma unroll
    for (int mi = 0; mi < 4; mi++)
        #pragma unroll
        for (int ni = 0; ni < 4; ni++)
            #pragma unroll
            for (int c = 0; c < 4; c++)
                acc[mi][ni][c] = 0.0f;

    float4 sa[4], sb[4];

    // Prologue: load + convert + store tile 0 into buffer 0.
    #pragma unroll
    for (int i = 0; i < 4; i++) {
        int lin = tid + 256 * i;
        int r   = lin >> 3;
        int c4  = (lin & 7) * 4;
        sa[i] = *(const float4*)(Ag + (size_t)(bm + r) * lda + c4);
        sb[i] = *(const float4*)(Bg + (size_t)(bn + r) * ldb + c4);
    }
    #pragma unroll
    for (int i = 0; i < 4; i++) {
        int lin = tid + 256 * i;
        int r   = lin >> 3;
        int g   = lin & 7;
        int off = r * 32 + ((g ^ (r & 7)) << 2);
        uint4 wa, wb;
        wa.x = f2tf32(sa[i].x); wa.y = f2tf32(sa[i].y);
        wa.z = f2tf32(sa[i].z); wa.w = f2tf32(sa[i].w);
        wb.x = f2tf32(sb[i].x); wb.y = f2tf32(sb[i].y);
        wb.z = f2tf32(sb[i].z); wb.w = f2tf32(sb[i].w);
        *(uint4*)(sm + off)        = wa;
        *(uint4*)(sm + 8192 + off) = wb;
    }
    __syncthreads();

    for (int k = 0; k < nk; k++) {
        const int buf = k & 1;

        // Stage tile k+1 from gmem into registers (latency hidden by MMA below).
        if (k + 1 < nk) {
            const int k0 = (k + 1) * KC;
            #pragma unroll
            for (int i = 0; i < 4; i++) {
                int lin = tid + 256 * i;
                int r   = lin >> 3;
                int c4  = (lin & 7) * 4;
                sa[i] = *(const float4*)(Ag + (size_t)(bm + r) * lda + k0 + c4);
                sb[i] = *(const float4*)(Bg + (size_t)(bn + r) * ldb + k0 + c4);
            }
        }

        // MMA over tile k (values already tf32 — no cvt in this loop).
        const uint32_t* Ab = sm + buf * 4096;
        const uint32_t* Bb = sm + 8192 + buf * 4096;
        #pragma unroll
        for (int kk = 0; kk < 4; kk++) {
            const int sw0 = (((2 * kk    ) ^ grp) << 2) + tig;
            const int sw1 = (((2 * kk + 1) ^ grp) << 2) + tig;
            uint32_t a[4][4];
            #pragma unroll
            for (int mi = 0; mi < 4; mi++) {
                const int ar = wm + mi * 16 + grp;
                a[mi][0] = Ab[ar * 32 + sw0];
                a[mi][1] = Ab[(ar + 8) * 32 + sw0];
                a[mi][2] = Ab[ar * 32 + sw1];
                a[mi][3] = Ab[(ar + 8) * 32 + sw1];
            }
            uint32_t b[4][2];
            #pragma unroll
            for (int ni = 0; ni < 4; ni++) {
                const int br = wn + ni * 8 + grp;
                b[ni][0] = Bb[br * 32 + sw0];
                b[ni][1] = Bb[br * 32 + sw1];
            }
            #pragma unroll
            for (int mi = 0; mi < 4; mi++)
                #pragma unroll
                for (int ni = 0; ni < 4; ni++)
                    mma_tf32(acc[mi][ni], a[mi], b[ni]);
        }
        __syncthreads();   // all warps done reading buf^1 (from iter k-1)

        // Convert + store tile k+1 into the other buffer.
        if (k + 1 < nk) {
            uint32_t* An = sm + ((k + 1) & 1) * 4096;
            uint32_t* Bn = sm + 8192 + ((k + 1) & 1) * 4096;
            #pragma unroll
            for (int i = 0; i < 4; i++) {
                int lin = tid + 256 * i;
                int r   = lin >> 3;
                int g   = lin & 7;
                int off = r * 32 + ((g ^ (r & 7)) << 2);
                uint4 wa, wb;
                wa.x = f2tf32(sa[i].x); wa.y = f2tf32(sa[i].y);
                wa.z = f2tf32(sa[i].z); wa.w = f2tf32(sa[i].w);
                wb.x = f2tf32(sb[i].x); wb.y = f2tf32(sb[i].y);
                wb.z = f2tf32(sb[i].z); wb.w = f2tf32(sb[i].w);
                *(uint4*)(An + off) = wa;
                *(uint4*)(Bn + off) = wb;
            }
        }
        __syncthreads();   // new tile visible before next MMA phase
    }

    // Epilogue: direct float2 stores (C fragment layout).
    #pragma unroll
    for (int mi = 0; mi < 4; mi++) {
        #pragma unroll
        for (int ni = 0; ni < 4; ni++) {
            const int r = bm + wm + mi * 16 + grp;
            const int c = bn + wn + ni * 8 + 2 * tig;
            float2 v0 = make_float2(acc[mi][ni][0], acc[mi][ni][1]);
            float2 v1 = make_float2(acc[mi][ni][2], acc[mi][ni][3]);
            *(float2*)&Dg[(size_t)r       * ldd + c] = v0;
            *(float2*)&Dg[(size_t)(r + 8) * ldd + c] = v1;
        }
    }
}

// ---------------------------------------------------------------------------
// V transpose: g_vt[e][p] = V[p][e]  (makes the AV GEMM plain K-major)
// ---------------------------------------------------------------------------
__global__ __launch_bounds__(256) void transpose_v(const float* __restrict__ V) {
    __shared__ float t[32][33];
    const int bx = blockIdx.x * 32;  // E
    const int by = blockIdx.y * 32;  // P
    const int tx = threadIdx.x;
    const int ty = threadIdx.y;
    #pragma unroll
    for (int j = 0; j < 32; j += 8)
        t[ty + j][tx] = V[(size_t)(by + ty + j) * E_DIM + bx + tx];
    __syncthreads();
    #pragma unroll
    for (int j = 0; j < 32; j += 8)
        g_vt[(size_t)(bx + ty + j) * P_DIM + by + tx] = t[tx][ty + j];
}

// ---------------------------------------------------------------------------
// Row softmax over P_DIM=4096, in place, float4 I/O. The 1/sqrt(E) score
// scale is folded in here: softmax(s*scale) == exp((s - max)*scale)/sum.
// ---------------------------------------------------------------------------
__global__ __launch_bounds__(256) void softmax_rows(float scale) {
    __shared__ float red[8];
    const int t    = threadIdx.x;
    const int lane = t & 31;
    const int w    = t >> 5;
    float4* sr = (float4*)(g_scores + (size_t)blockIdx.x * P_DIM);

    float4 v[4];
    float m = -3.0e38f;
    #pragma unroll
    for (int j = 0; j < 4; j++) {
        v[j] = sr[t + 256 * j];
        m = fmaxf(m, fmaxf(fmaxf(v[j].x, v[j].y), fmaxf(v[j].z, v[j].w)));
    }
    #pragma unroll
    for (int o = 16; o > 0; o >>= 1)
        m = fmaxf(m, __shfl_xor_sync(0xffffffffu, m, o));
    if (lane == 0) red[w] = m;
    __syncthreads();
    m = red[0];
    #pragma unroll
    for (int i = 1; i < 8; i++) m = fmaxf(m, red[i]);

    float s = 0.0f;
    #pragma unroll
    for (int j = 0; j < 4; j++) {
        v[j].x = __expf((v[j].x - m) * scale);
        v[j].y = __expf((v[j].y - m) * scale);
        v[j].z = __expf((v[j].z - m) * scale);
        v[j].w = __expf((v[j].w - m) * scale);
        s += v[j].x + v[j].y + v[j].z + v[j].w;
    }
    #pragma unroll
    for (int o = 16; o > 0; o >>= 1)
        s += __shfl_xor_sync(0xffffffffu, s, o);
    __syncthreads();
    if (lane == 0) red[w] = s;
    __syncthreads();
    s = 0.0f;
    #pragma unroll
    for (int i = 0; i < 8; i++) s += red[i];
    const float inv = 1.0f / s;

    #pragma unroll
    for (int j = 0; j < 4; j++) {
        v[j].x *= inv; v[j].y *= inv; v[j].z *= inv; v[j].w *= inv;
        sr[t + 256 * j] = v[j];
    }
}

// ---------------------------------------------------------------------------
// Launch. Inputs: x [4,2048,1024], K [4096,1024], V [4096,1024]; out fp32.
// Only kernel launches are enqueued -> graph-capturable; attribute/symbol
// queries execute immediately and are deterministic.
// ---------------------------------------------------------------------------
extern "C" void kernel_launch(void* const* d_in, const int* in_sizes, int n_in,
                              void* d_out, int out_size) {
    (void)in_sizes; (void)n_in; (void)out_size;
    const float* x  = (const float*)d_in[0];
    const float* Kw = (const float*)d_in[1];
    const float* V  = (const float*)d_in[2];
    float* out = (float*)d_out;

    cudaFuncSetAttribute(gemm_tc, cudaFuncAttributeMaxDynamicSharedMemorySize,
                         SMEM_BYTES);

    void* p_scores = nullptr;
    void* p_vt = nullptr;
    cudaGetSymbolAddress(&p_scores, g_scores);
    cudaGetSymbolAddress(&p_vt, g_vt);
    float* scores = (float*)p_scores;
    float* vt = (float*)p_vt;

    // V^T for the AV GEMM
    transpose_v<<<dim3(E_DIM / 32, P_DIM / 32), dim3(32, 8)>>>(V);

    // raw scores = x @ K^T   (scale folded into softmax)
    gemm_tc<<<dim3(P_DIM / BN, M_TOTAL / BM), 256, SMEM_BYTES>>>(
        x, Kw, scores, E_DIM / KC, E_DIM, E_DIM, P_DIM);

    softmax_rows<<<M_TOTAL, 256>>>(0.03125f);

    // out = attn @ V   (B = V^T, K-major over P)
    gemm_tc<<<dim3(E_DIM / BN, M_TOTAL / BM), 256, SMEM_BYTES>>>(
        scores, vt, out, P_DIM / KC, P_DIM, P_DIM, E_DIM);
}

// round 6
// speedup vs baseline: 2.1298x; 1.5140x over previous
#include <cuda_runtime.h>
#include <stdint.h>

// ---------------------------------------------------------------------------
// Problem dims (fixed by the dataset)
// ---------------------------------------------------------------------------
#define M_TOTAL 8192   // B*S = 4*2048
#define E_DIM   1024
#define P_DIM   4096

// Device scratch (__device__ globals = sanctioned scratch)
__device__ float g_scores[(size_t)M_TOTAL * (size_t)P_DIM];  // 128 MB
__device__ float g_xt[(size_t)M_TOTAL * (size_t)E_DIM];      // 32 MB, tf32(x)
__device__ float g_kt[(size_t)P_DIM * (size_t)E_DIM];        // 16 MB, tf32(K)
__device__ float g_vt[(size_t)E_DIM * (size_t)P_DIM];        // 16 MB, tf32(V^T)

// ---------------------------------------------------------------------------
// Helpers
// ---------------------------------------------------------------------------
__device__ __forceinline__ uint32_t f2tf32(float x) {
    uint32_t r;
    asm("cvt.rna.tf32.f32 %0, %1;" : "=r"(r) : "f"(x));
    return r;
}

__device__ __forceinline__ uint32_t smem_u32(const void* p) {
    uint32_t a;
    asm("{ .reg .u64 t; cvta.to.shared.u64 t, %1; cvt.u32.u64 %0, t; }"
        : "=r"(a) : "l"(p));
    return a;
}

__device__ __forceinline__ void cp_async16(uint32_t dst, const void* src) {
    asm volatile("cp.async.cg.shared.global [%0], [%1], 16;"
                 :: "r"(dst), "l"(src) : "memory");
}
#define CP_ASYNC_COMMIT() asm volatile("cp.async.commit_group;" ::: "memory")
#define CP_ASYNC_WAIT_1() asm volatile("cp.async.wait_group 1;" ::: "memory")

__device__ __forceinline__ void mma_tf32(float c[4], const uint32_t a[4], const uint32_t b[2]) {
    asm volatile(
        "mma.sync.aligned.m16n8k8.row.col.f32.tf32.tf32.f32 "
        "{%0,%1,%2,%3}, {%4,%5,%6,%7}, {%8,%9}, {%0,%1,%2,%3};"
        : "+f"(c[0]), "+f"(c[1]), "+f"(c[2]), "+f"(c[3])
        : "r"(a[0]), "r"(a[1]), "r"(a[2]), "r"(a[3]),
          "r"(b[0]), "r"(b[1]));
}

// ---------------------------------------------------------------------------
// GEMM: D[m,n] = sum_k A[m,k]*B[n,k]; A,B already tf32-rounded in gmem.
// CTA 128(M) x 256(N), KC=32, 512 threads = 16 warps (2x8), warp tile 64x32.
// cp.async 3-stage pipeline; one __syncthreads per k-tile.
//
// SMEM per stage: A 4096 words, B 8192 words (stage stride 12288 words).
// XOR swizzle in 32-word rows: word(r,c) -> r*32 + ((c>>2)^(r&7))*4 + (c&3).
//  - cp.async 16B stores: quarter-warp hits one row, 8 distinct groups -> CF
//  - LDS.32 fragment reads: banks 4*((2kk+h)^grp)+tig cover 0..31 -> CF
// ---------------------------------------------------------------------------
#define BM 128
#define BN 256
#define KC 32
#define STAGES 3
#define STG_WORDS 12288
#define SMEM_BYTES (STAGES * STG_WORDS * 4)   // 147456

__global__ __launch_bounds__(512, 1) void gemm_tc(const float* __restrict__ Ag,
                                                  const float* __restrict__ Bg,
                                                  float* __restrict__ Dg,
                                                  int nk, int lda, int ldb, int ldd) {
    extern __shared__ uint32_t sm[];
    const uint32_t sbase = smem_u32(sm);
    const int tid  = threadIdx.x;
    const int lane = tid & 31;
    const int wid  = tid >> 5;
    const int wm   = (wid >> 3) * 64;   // 2 warps in M
    const int wn   = (wid & 7) * 32;    // 8 warps in N
    const int bm   = blockIdx.y * BM;
    const int bn   = blockIdx.x * BN;
    const int tig  = lane & 3;
    const int grp  = lane >> 2;

    // Per-thread copy-slot geometry (16B chunks, 8 per 32-word row)
    // A: 1024 chunks -> 2/thread; B: 2048 chunks -> 4/thread.
    auto issue_stage = [&](int stage, int k0) {
        const uint32_t abase = sbase + (uint32_t)stage * (STG_WORDS * 4);
        const uint32_t bbase = abase + 4096 * 4;
        #pragma unroll
        for (int i = 0; i < 2; i++) {
            int lin = tid + 512 * i;
            int r   = lin >> 3;
            int g   = lin & 7;
            uint32_t woff = (uint32_t)(r * 32 + ((g ^ (r & 7)) << 2));
            cp_async16(abase + woff * 4, Ag + (size_t)(bm + r) * lda + k0 + g * 4);
        }
        #pragma unroll
        for (int i = 0; i < 4; i++) {
            int lin = tid + 512 * i;
            int r   = lin >> 3;
            int g   = lin & 7;
            uint32_t woff = (uint32_t)(r * 32 + ((g ^ (r & 7)) << 2));
            cp_async16(bbase + woff * 4, Bg + (size_t)(bn + r) * ldb + k0 + g * 4);
        }
    };

    float acc[4][4][4];
    #pragma unroll
    for (int mi = 0; mi < 4; mi++)
        #pragma unroll
        for (int ni = 0; ni < 4; ni++)
            #pragma unroll
            for (int c = 0; c < 4; c++)
                acc[mi][ni][c] = 0.0f;

    // Prologue: stages 0..STAGES-2
    issue_stage(0, 0);
    CP_ASYNC_COMMIT();
    issue_stage(1, KC);
    CP_ASYNC_COMMIT();

    int stage_rd = 0;
    int stage_wr = 2;
    for (int k = 0; k < nk; k++) {
        CP_ASYNC_WAIT_1();
        __syncthreads();

        const uint32_t* Ab = sm + stage_rd * STG_WORDS;
        const uint32_t* Bb = Ab + 4096;
        #pragma unroll
        for (int kk = 0; kk < 4; kk++) {
            const int sw0 = (((2 * kk    ) ^ grp) << 2) + tig;
            const int sw1 = (((2 * kk + 1) ^ grp) << 2) + tig;
            uint32_t a[4][4];
            #pragma unroll
            for (int mi = 0; mi < 4; mi++) {
                const int ar = wm + mi * 16 + grp;
                a[mi][0] = Ab[ar * 32 + sw0];
                a[mi][1] = Ab[(ar + 8) * 32 + sw0];
                a[mi][2] = Ab[ar * 32 + sw1];
                a[mi][3] = Ab[(ar + 8) * 32 + sw1];
            }
            uint32_t b[4][2];
            #pragma unroll
            for (int ni = 0; ni < 4; ni++) {
                const int br = wn + ni * 8 + grp;
                b[ni][0] = Bb[br * 32 + sw0];
                b[ni][1] = Bb[br * 32 + sw1];
            }
            #pragma unroll
            for (int mi = 0; mi < 4; mi++)
                #pragma unroll
                for (int ni = 0; ni < 4; ni++)
                    mma_tf32(acc[mi][ni], a[mi], b[ni]);
        }

        // Issue tile k+STAGES-1 into the buffer freed at iter k-1.
        if (k + STAGES - 1 < nk)
            issue_stage(stage_wr, (k + STAGES - 1) * KC);
        CP_ASYNC_COMMIT();   // commit every iter (possibly empty group)

        stage_rd = (stage_rd + 1 == STAGES) ? 0 : stage_rd + 1;
        stage_wr = (stage_wr + 1 == STAGES) ? 0 : stage_wr + 1;
    }

    // Epilogue: direct float2 stores (C fragment layout).
    #pragma unroll
    for (int mi = 0; mi < 4; mi++) {
        #pragma unroll
        for (int ni = 0; ni < 4; ni++) {
            const int r = bm + wm + mi * 16 + grp;
            const int c = bn + wn + ni * 8 + 2 * tig;
            float2 v0 = make_float2(acc[mi][ni][0], acc[mi][ni][1]);
            float2 v1 = make_float2(acc[mi][ni][2], acc[mi][ni][3]);
            *(float2*)&Dg[(size_t)r       * ldd + c] = v0;
            *(float2*)&Dg[(size_t)(r + 8) * ldd + c] = v1;
        }
    }
}

// ---------------------------------------------------------------------------
// Elementwise tf32 convert: dst[i] = tf32_rna(src[i])
// ---------------------------------------------------------------------------
__global__ __launch_bounds__(256) void cvt_copy(const float* __restrict__ src,
                                                float* __restrict__ dst) {
    const size_t i = ((size_t)blockIdx.x * 256 + threadIdx.x) * 4;
    float4 v = *(const float4*)(src + i);
    uint4 w;
    w.x = f2tf32(v.x); w.y = f2tf32(v.y);
    w.z = f2tf32(v.z); w.w = f2tf32(v.w);
    *(uint4*)(dst + i) = w;
}

// ---------------------------------------------------------------------------
// V transpose + tf32 convert: g_vt[e][p] = tf32(V[p][e])
// ---------------------------------------------------------------------------
__global__ __launch_bounds__(256) void transpose_v(const float* __restrict__ V) {
    __shared__ float t[32][33];
    const int bx = blockIdx.x * 32;  // E
    const int by = blockIdx.y * 32;  // P
    const int tx = threadIdx.x;
    const int ty = threadIdx.y;
    #pragma unroll
    for (int j = 0; j < 32; j += 8)
        t[ty + j][tx] = V[(size_t)(by + ty + j) * E_DIM + bx + tx];
    __syncthreads();
    #pragma unroll
    for (int j = 0; j < 32; j += 8)
        *(uint32_t*)&g_vt[(size_t)(bx + ty + j) * P_DIM + by + tx] =
            f2tf32(t[tx][ty + j]);
}

// ---------------------------------------------------------------------------
// Row softmax over P_DIM=4096, in place; 1/sqrt(E) folded in; output rounded
// to tf32 so the AV GEMM needs no conversion.
// ---------------------------------------------------------------------------
__global__ __launch_bounds__(256) void softmax_rows(float scale) {
    __shared__ float red[8];
    const int t    = threadIdx.x;
    const int lane = t & 31;
    const int w    = t >> 5;
    float4* sr = (float4*)(g_scores + (size_t)blockIdx.x * P_DIM);

    float4 v[4];
    float m = -3.0e38f;
    #pragma unroll
    for (int j = 0; j < 4; j++) {
        v[j] = sr[t + 256 * j];
        m = fmaxf(m, fmaxf(fmaxf(v[j].x, v[j].y), fmaxf(v[j].z, v[j].w)));
    }
    #pragma unroll
    for (int o = 16; o > 0; o >>= 1)
        m = fmaxf(m, __shfl_xor_sync(0xffffffffu, m, o));
    if (lane == 0) red[w] = m;
    __syncthreads();
    m = red[0];
    #pragma unroll
    for (int i = 1; i < 8; i++) m = fmaxf(m, red[i]);

    float s = 0.0f;
    #pragma unroll
    for (int j = 0; j < 4; j++) {
        v[j].x = __expf((v[j].x - m) * scale);
        v[j].y = __expf((v[j].y - m) * scale);
        v[j].z = __expf((v[j].z - m) * scale);
        v[j].w = __expf((v[j].w - m) * scale);
        s += v[j].x + v[j].y + v[j].z + v[j].w;
    }
    #pragma unroll
    for (int o = 16; o > 0; o >>= 1)
        s += __shfl_xor_sync(0xffffffffu, s, o);
    __syncthreads();
    if (lane == 0) red[w] = s;
    __syncthreads();
    s = 0.0f;
    #pragma unroll
    for (int i = 0; i < 8; i++) s += red[i];
    const float inv = 1.0f / s;

    #pragma unroll
    for (int j = 0; j < 4; j++) {
        uint4 o;
        o.x = f2tf32(v[j].x * inv);
        o.y = f2tf32(v[j].y * inv);
        o.z = f2tf32(v[j].z * inv);
        o.w = f2tf32(v[j].w * inv);
        *(uint4*)&sr[t + 256 * j] = o;
    }
}

// ---------------------------------------------------------------------------
// Launch. Inputs: x [4,2048,1024], K [4096,1024], V [4096,1024]; out fp32.
// Only kernel launches enqueued -> graph-capturable.
// ---------------------------------------------------------------------------
extern "C" void kernel_launch(void* const* d_in, const int* in_sizes, int n_in,
                              void* d_out, int out_size) {
    (void)in_sizes; (void)n_in; (void)out_size;
    const float* x  = (const float*)d_in[0];
    const float* Kw = (const float*)d_in[1];
    const float* V  = (const float*)d_in[2];
    float* out = (float*)d_out;

    cudaFuncSetAttribute(gemm_tc, cudaFuncAttributeMaxDynamicSharedMemorySize,
                         SMEM_BYTES);

    void *p_scores, *p_xt, *p_kt, *p_vt;
    cudaGetSymbolAddress(&p_scores, g_scores);
    cudaGetSymbolAddress(&p_xt, g_xt);
    cudaGetSymbolAddress(&p_kt, g_kt);
    cudaGetSymbolAddress(&p_vt, g_vt);
    float* scores = (float*)p_scores;
    float* xt = (float*)p_xt;
    float* kt = (float*)p_kt;
    float* vt = (float*)p_vt;

    // Pre-convert inputs to tf32 (once); transpose+convert V.
    cvt_copy<<<(M_TOTAL * E_DIM) / 1024, 256>>>(x, xt);
    cvt_copy<<<(P_DIM * E_DIM) / 1024, 256>>>(Kw, kt);
    transpose_v<<<dim3(E_DIM / 32, P_DIM / 32), dim3(32, 8)>>>(V);

    // raw scores = x @ K^T (scale folded into softmax)
    gemm_tc<<<dim3(P_DIM / BN, M_TOTAL / BM), 512, SMEM_BYTES>>>(
        xt, kt, scores, E_DIM / KC, E_DIM, E_DIM, P_DIM);

    softmax_rows<<<M_TOTAL, 256>>>(0.03125f);

    // out = attn @ V (B = V^T, K-major over P)
    gemm_tc<<<dim3(E_DIM / BN, M_TOTAL / BM), 512, SMEM_BYTES>>>(
        scores, vt, out, P_DIM / KC, P_DIM, P_DIM, E_DIM);
}

// round 9
// speedup vs baseline: 2.3445x; 1.1008x over previous
#include <cuda_runtime.h>
#include <stdint.h>

// ---------------------------------------------------------------------------
// Problem dims (fixed by the dataset)
// ---------------------------------------------------------------------------
#define M_TOTAL 8192   // B*S = 4*2048
#define E_DIM   1024
#define P_DIM   4096

// Device scratch (__device__ globals = sanctioned scratch)
__device__ float g_scores[(size_t)M_TOTAL * (size_t)P_DIM];  // 128 MB
__device__ float g_xt[(size_t)M_TOTAL * (size_t)E_DIM];      // 32 MB, tf32(x)
__device__ float g_kt[(size_t)P_DIM * (size_t)E_DIM];        // 16 MB, tf32(K)
__device__ float g_vt[(size_t)E_DIM * (size_t)P_DIM];        // 16 MB, tf32(V^T)

// ---------------------------------------------------------------------------
// Helpers
// ---------------------------------------------------------------------------
__device__ __forceinline__ uint32_t f2tf32(float x) {
    uint32_t r;
    asm("cvt.rna.tf32.f32 %0, %1;" : "=r"(r) : "f"(x));
    return r;
}

__device__ __forceinline__ uint32_t smem_u32(const void* p) {
    uint32_t a;
    asm("{ .reg .u64 t; cvta.to.shared.u64 t, %1; cvt.u32.u64 %0, t; }"
        : "=r"(a) : "l"(p));
    return a;
}

__device__ __forceinline__ void cp_async16(uint32_t dst, const void* src) {
    asm volatile("cp.async.cg.shared.global [%0], [%1], 16;"
                 :: "r"(dst), "l"(src) : "memory");
}
#define CP_ASYNC_COMMIT() asm volatile("cp.async.commit_group;" ::: "memory")
#define CP_ASYNC_WAIT_1() asm volatile("cp.async.wait_group 1;" ::: "memory")

// ldmatrix: for tf32 data each m8n8.b16 tile == 8 rows x 4 tf32; lane l gets
// element (row=l>>2, col=l&3) == the (grp,tig) fragment mapping of m16n8k8.
__device__ __forceinline__ void ldsm_x4(uint32_t r[4], uint32_t addr) {
    asm volatile("ldmatrix.sync.aligned.m8n8.x4.shared.b16 {%0,%1,%2,%3}, [%4];"
                 : "=r"(r[0]), "=r"(r[1]), "=r"(r[2]), "=r"(r[3]) : "r"(addr));
}
__device__ __forceinline__ void ldsm_x2(uint32_t r[2], uint32_t addr) {
    asm volatile("ldmatrix.sync.aligned.m8n8.x2.shared.b16 {%0,%1}, [%2];"
                 : "=r"(r[0]), "=r"(r[1]) : "r"(addr));
}

__device__ __forceinline__ void mma_tf32(float c[4], const uint32_t a[4], const uint32_t b[2]) {
    asm volatile(
        "mma.sync.aligned.m16n8k8.row.col.f32.tf32.tf32.f32 "
        "{%0,%1,%2,%3}, {%4,%5,%6,%7}, {%8,%9}, {%0,%1,%2,%3};"
        : "+f"(c[0]), "+f"(c[1]), "+f"(c[2]), "+f"(c[3])
        : "r"(a[0]), "r"(a[1]), "r"(a[2]), "r"(a[3]),
          "r"(b[0]), "r"(b[1]));
}

// ---------------------------------------------------------------------------
// GEMM: D[m,n] = sum_k A[m,k]*B[n,k]; A,B already tf32-rounded in gmem.
// CTA 128(M) x 256(N), KC=32, 512 threads = 16 warps (2x8), warp tile 64x32.
// cp.async 3-stage pipeline (next tile issued BEFORE the MMA phase).
//
// SMEM per stage: A 4096 words, B 8192 words (stage stride 12288 words).
// XOR swizzle in 32-word rows: word(r,c) -> r*32 + ((c>>2)^(r&7))*4 + (c&3)
// (byte addr: r*128 + ((g^(r&7))<<4) + ..., g = 16B-group = c>>2).
//  - cp.async 16B stores conflict-free; ldmatrix phases conflict-free
//    (per phase: 8 rows, bank groups 4*(g^r) distinct, all 32 banks).
// ---------------------------------------------------------------------------
#define BM 128
#define BN 256
#define KC 32
#define STAGES 3
#define STG_WORDS 12288
#define SMEM_BYTES (STAGES * STG_WORDS * 4)   // 147456

__global__ __launch_bounds__(512, 1) void gemm_tc(const float* __restrict__ Ag,
                                                  const float* __restrict__ Bg,
                                                  float* __restrict__ Dg,
                                                  int nk, int lda, int ldb, int ldd) {
    extern __shared__ uint32_t sm[];
    const uint32_t sbase = smem_u32(sm);
    const int tid  = threadIdx.x;
    const int lane = tid & 31;
    const int wid  = tid >> 5;
    const int wm   = (wid >> 3) * 64;   // 2 warps in M
    const int wn   = (wid & 7) * 32;    // 8 warps in N
    const int bm   = blockIdx.y * BM;
    const int bn   = blockIdx.x * BN;
    const int tig  = lane & 3;
    const int grp  = lane >> 2;

    // --- ldmatrix per-lane address precompute -----------------------------
    // A x4: matrices {rows 0-7, rows 8-15} x {kgrp, kgrp+1};
    //   lane row = (lane&15), k-group flag = lane>>4.
    // B x2: matrices {kgrp, kgrp+1}; lanes 0-15: row = lane&7, flag=(lane>>3)&1.
    const int gflA = lane >> 4;
    const int gflB = (lane >> 3) & 1;
    uint32_t preA[4]; int rb7A[4];
    #pragma unroll
    for (int mi = 0; mi < 4; mi++) {
        int r = wm + mi * 16 + (lane & 15);
        preA[mi] = (uint32_t)(r * 128);
        rb7A[mi] = r & 7;
    }
    uint32_t preB[4]; int rb7B[4];
    #pragma unroll
    for (int ni = 0; ni < 4; ni++) {
        int r = wn + ni * 8 + (lane & 7);
        preB[ni] = (uint32_t)(r * 128);
        rb7B[ni] = r & 7;
    }

    // Per-thread copy-slot geometry (16B chunks, 8 per 32-word row)
    auto issue_stage = [&](int stage, int k0) {
        const uint32_t abase = sbase + (uint32_t)stage * (STG_WORDS * 4);
        const uint32_t bbase = abase + 4096 * 4;
        #pragma unroll
        for (int i = 0; i < 2; i++) {
            int lin = tid + 512 * i;
            int r   = lin >> 3;
            int g   = lin & 7;
            uint32_t boff = (uint32_t)(r * 128 + ((g ^ (r & 7)) << 4));
            cp_async16(abase + boff, Ag + (size_t)(bm + r) * lda + k0 + g * 4);
        }
        #pragma unroll
        for (int i = 0; i < 4; i++) {
            int lin = tid + 512 * i;
            int r   = lin >> 3;
            int g   = lin & 7;
            uint32_t boff = (uint32_t)(r * 128 + ((g ^ (r & 7)) << 4));
            cp_async16(bbase + boff, Bg + (size_t)(bn + r) * ldb + k0 + g * 4);
        }
    };

    float acc[4][4][4];
    #pragma unroll
    for (int mi = 0; mi < 4; mi++)
        #pragma unroll
        for (int ni = 0; ni < 4; ni++)
            #pragma unroll
            for (int c = 0; c < 4; c++)
                acc[mi][ni][c] = 0.0f;

    // Prologue: stages 0..1
    issue_stage(0, 0);
    CP_ASYNC_COMMIT();
    issue_stage(1, KC);
    CP_ASYNC_COMMIT();

    int stage_rd = 0;
    int stage_wr = 2;
    for (int k = 0; k < nk; k++) {
        CP_ASYNC_WAIT_1();
        __syncthreads();

        // Issue tile k+2 into the buffer freed at iter k-1 (before MMA so the
        // LDGSTS latency is covered by this iteration's tensor work).
        if (k + STAGES - 1 < nk)
            issue_stage(stage_wr, (k + STAGES - 1) * KC);
        CP_ASYNC_COMMIT();

        const uint32_t astage = sbase + (uint32_t)stage_rd * (STG_WORDS * 4);
        const uint32_t bstage = astage + 4096 * 4;
        #pragma unroll
        for (int kk = 0; kk < 4; kk++) {
            uint32_t a[4][4];
            #pragma unroll
            for (int mi = 0; mi < 4; mi++) {
                uint32_t addr = astage + preA[mi] +
                                (uint32_t)((((2 * kk + gflA) ^ rb7A[mi])) << 4);
                ldsm_x4(a[mi], addr);
            }
            uint32_t b[4][2];
            #pragma unroll
            for (int ni = 0; ni < 4; ni++) {
                uint32_t addr = bstage + preB[ni] +
                                (uint32_t)((((2 * kk + gflB) ^ rb7B[ni])) << 4);
                ldsm_x2(b[ni], addr);
            }
            #pragma unroll
            for (int mi = 0; mi < 4; mi++)
                #pragma unroll
                for (int ni = 0; ni < 4; ni++)
                    mma_tf32(acc[mi][ni], a[mi], b[ni]);
        }

        stage_rd = (stage_rd + 1 == STAGES) ? 0 : stage_rd + 1;
        stage_wr = (stage_wr + 1 == STAGES) ? 0 : stage_wr + 1;
    }

    // Epilogue: direct float2 stores (C fragment layout; 32B-sector aligned).
    #pragma unroll
    for (int mi = 0; mi < 4; mi++) {
        #pragma unroll
        for (int ni = 0; ni < 4; ni++) {
            const int r = bm + wm + mi * 16 + grp;
            const int c = bn + wn + ni * 8 + 2 * tig;
            float2 v0 = make_float2(acc[mi][ni][0], acc[mi][ni][1]);
            float2 v1 = make_float2(acc[mi][ni][2], acc[mi][ni][3]);
            *(float2*)&Dg[(size_t)r       * ldd + c] = v0;
            *(float2*)&Dg[(size_t)(r + 8) * ldd + c] = v1;
        }
    }
}

// ---------------------------------------------------------------------------
// Elementwise tf32 convert: dst[i] = tf32_rna(src[i])
// ---------------------------------------------------------------------------
__global__ __launch_bounds__(256) void cvt_copy(const float* __restrict__ src,
                                                float* __restrict__ dst) {
    const size_t i = ((size_t)blockIdx.x * 256 + threadIdx.x) * 4;
    float4 v = *(const float4*)(src + i);
    uint4 w;
    w.x = f2tf32(v.x); w.y = f2tf32(v.y);
    w.z = f2tf32(v.z); w.w = f2tf32(v.w);
    *(uint4*)(dst + i) = w;
}

// ---------------------------------------------------------------------------
// V transpose + tf32 convert: g_vt[e][p] = tf32(V[p][e])
// ---------------------------------------------------------------------------
__global__ __launch_bounds__(256) void transpose_v(const float* __restrict__ V) {
    __shared__ float t[32][33];
    const int bx = blockIdx.x * 32;  // E
    const int by = blockIdx.y * 32;  // P
    const int tx = threadIdx.x;
    const int ty = threadIdx.y;
    #pragma unroll
    for (int j = 0; j < 32; j += 8)
        t[ty + j][tx] = V[(size_t)(by + ty + j) * E_DIM + bx + tx];
    __syncthreads();
    #pragma unroll
    for (int j = 0; j < 32; j += 8)
        *(uint32_t*)&g_vt[(size_t)(bx + ty + j) * P_DIM + by + tx] =
            f2tf32(t[tx][ty + j]);
}

// ---------------------------------------------------------------------------
// Row softmax over P_DIM=4096, in place; 1/sqrt(E) folded in; output rounded
// to tf32 so the AV GEMM needs no conversion.
// ---------------------------------------------------------------------------
__global__ __launch_bounds__(256) void softmax_rows(float scale) {
    __shared__ float red[8];
    const int t    = threadIdx.x;
    const int lane = t & 31;
    const int w    = t >> 5;
    float4* sr = (float4*)(g_scores + (size_t)blockIdx.x * P_DIM);

    float4 v[4];
    float m = -3.0e38f;
    #pragma unroll
    for (int j = 0; j < 4; j++) {
        v[j] = sr[t + 256 * j];
        m = fmaxf(m, fmaxf(fmaxf(v[j].x, v[j].y), fmaxf(v[j].z, v[j].w)));
    }
    #pragma unroll
    for (int o = 16; o > 0; o >>= 1)
        m = fmaxf(m, __shfl_xor_sync(0xffffffffu, m, o));
    if (lane == 0) red[w] = m;
    __syncthreads();
    m = red[0];
    #pragma unroll
    for (int i = 1; i < 8; i++) m = fmaxf(m, red[i]);

    float s = 0.0f;
    #pragma unroll
    for (int j = 0; j < 4; j++) {
        v[j].x = __expf((v[j].x - m) * scale);
        v[j].y = __expf((v[j].y - m) * scale);
        v[j].z = __expf((v[j].z - m) * scale);
        v[j].w = __expf((v[j].w - m) * scale);
        s += v[j].x + v[j].y + v[j].z + v[j].w;
    }
    #pragma unroll
    for (int o = 16; o > 0; o >>= 1)
        s += __shfl_xor_sync(0xffffffffu, s, o);
    __syncthreads();
    if (lane == 0) red[w] = s;
    __syncthreads();
    s = 0.0f;
    #pragma unroll
    for (int i = 0; i < 8; i++) s += red[i];
    const float inv = 1.0f / s;

    #pragma unroll
    for (int j = 0; j < 4; j++) {
        uint4 o;
        o.x = f2tf32(v[j].x * inv);
        o.y = f2tf32(v[j].y * inv);
        o.z = f2tf32(v[j].z * inv);
        o.w = f2tf32(v[j].w * inv);
        *(uint4*)&sr[t + 256 * j] = o;
    }
}

// ---------------------------------------------------------------------------
// Launch. Inputs: x [4,2048,1024], K [4096,1024], V [4096,1024]; out fp32.
// Only kernel launches enqueued -> graph-capturable.
// ---------------------------------------------------------------------------
extern "C" void kernel_launch(void* const* d_in, const int* in_sizes, int n_in,
                              void* d_out, int out_size) {
    (void)in_sizes; (void)n_in; (void)out_size;
    const float* x  = (const float*)d_in[0];
    const float* Kw = (const float*)d_in[1];
    const float* V  = (const float*)d_in[2];
    float* out = (float*)d_out;

    cudaFuncSetAttribute(gemm_tc, cudaFuncAttributeMaxDynamicSharedMemorySize,
                         SMEM_BYTES);

    void *p_scores, *p_xt, *p_kt, *p_vt;
    cudaGetSymbolAddress(&p_scores, g_scores);
    cudaGetSymbolAddress(&p_xt, g_xt);
    cudaGetSymbolAddress(&p_kt, g_kt);
    cudaGetSymbolAddress(&p_vt, g_vt);
    float* scores = (float*)p_scores;
    float* xt = (float*)p_xt;
    float* kt = (float*)p_kt;
    float* vt = (float*)p_vt;

    // Pre-convert inputs to tf32 (once); transpose+convert V.
    cvt_copy<<<(M_TOTAL * E_DIM) / 1024, 256>>>(x, xt);
    cvt_copy<<<(P_DIM * E_DIM) / 1024, 256>>>(Kw, kt);
    transpose_v<<<dim3(E_DIM / 32, P_DIM / 32), dim3(32, 8)>>>(V);

    // raw scores = x @ K^T (scale folded into softmax)
    gemm_tc<<<dim3(P_DIM / BN, M_TOTAL / BM), 512, SMEM_BYTES>>>(
        xt, kt, scores, E_DIM / KC, E_DIM, E_DIM, P_DIM);

    softmax_rows<<<M_TOTAL, 256>>>(0.03125f);

    // out = attn @ V (B = V^T, K-major over P)
    gemm_tc<<<dim3(E_DIM / BN, M_TOTAL / BM), 512, SMEM_BYTES>>>(
        scores, vt, out, P_DIM / KC, P_DIM, P_DIM, E_DIM);
}

// round 10
// speedup vs baseline: 2.3849x; 1.0172x over previous
#include <cuda_runtime.h>
#include <stdint.h>

// ---------------------------------------------------------------------------
// Problem dims (fixed by the dataset)
// ---------------------------------------------------------------------------
#define M_TOTAL 8192   // B*S = 4*2048
#define E_DIM   1024
#define P_DIM   4096

// Device scratch (__device__ globals = sanctioned scratch)
__device__ float g_scores[(size_t)M_TOTAL * (size_t)P_DIM];  // 128 MB
__device__ float g_xt[(size_t)M_TOTAL * (size_t)E_DIM];      // 32 MB, tf32(x)
__device__ float g_kt[(size_t)P_DIM * (size_t)E_DIM];        // 16 MB, tf32(K)
__device__ float g_vt[(size_t)E_DIM * (size_t)P_DIM];        // 16 MB, tf32(V^T)

// ---------------------------------------------------------------------------
// Helpers
// ---------------------------------------------------------------------------
__device__ __forceinline__ uint32_t f2tf32(float x) {
    uint32_t r;
    asm("cvt.rna.tf32.f32 %0, %1;" : "=r"(r) : "f"(x));
    return r;
}

__device__ __forceinline__ uint32_t smem_u32(const void* p) {
    uint32_t a;
    asm("{ .reg .u64 t; cvta.to.shared.u64 t, %1; cvt.u32.u64 %0, t; }"
        : "=r"(a) : "l"(p));
    return a;
}

__device__ __forceinline__ void cp_async16(uint32_t dst, const void* src) {
    asm volatile("cp.async.cg.shared.global [%0], [%1], 16;"
                 :: "r"(dst), "l"(src) : "memory");
}
#define CP_ASYNC_COMMIT() asm volatile("cp.async.commit_group;" ::: "memory")
#define CP_ASYNC_WAIT_1() asm volatile("cp.async.wait_group 1;" ::: "memory")

// ldmatrix: for tf32 data each m8n8.b16 tile == 8 rows x 4 tf32; lane l gets
// element (row=l>>2, col=l&3) == the (grp,tig) fragment mapping of m16n8k8.
__device__ __forceinline__ void ldsm_x4(uint32_t r[4], uint32_t addr) {
    asm volatile("ldmatrix.sync.aligned.m8n8.x4.shared.b16 {%0,%1,%2,%3}, [%4];"
                 : "=r"(r[0]), "=r"(r[1]), "=r"(r[2]), "=r"(r[3]) : "r"(addr));
}

__device__ __forceinline__ void mma_tf32(float c[4], const uint32_t a[4], const uint32_t b[2]) {
    asm volatile(
        "mma.sync.aligned.m16n8k8.row.col.f32.tf32.tf32.f32 "
        "{%0,%1,%2,%3}, {%4,%5,%6,%7}, {%8,%9}, {%0,%1,%2,%3};"
        : "+f"(c[0]), "+f"(c[1]), "+f"(c[2]), "+f"(c[3])
        : "r"(a[0]), "r"(a[1]), "r"(a[2]), "r"(a[3]),
          "r"(b[0]), "r"(b[1]));
}

// ---------------------------------------------------------------------------
// GEMM: D[m,n] = sum_k A[m,k]*B[n,k]; A,B already tf32-rounded in gmem.
// CTA 128(M) x 256(N), KC=32, 512 threads = 16 warps (2x8), warp tile 64x32.
// cp.async 3-stage pipeline (next tile issued BEFORE the MMA phase).
//
// SMEM per stage: A 4096 words, B 8192 words (stage stride 12288 words).
// XOR swizzle in 32-word rows: word(r,c) -> r*32 + ((c>>2)^(r&7))*4 + (c&3)
// (byte addr: r*128 + ((g^(r&7))<<4)).
//  - cp.async 16B stores conflict-free; every ldmatrix phase reads 8 rows
//    with distinct (r&7) -> bank groups 4*(g^r) cover all 32 banks -> CF.
//
// A fragments via ldmatrix.x4 (one per mi: 2 row-blocks x 2 k-groups).
// B fragments via ldmatrix.x4 PAIRED: one x4 covers two adjacent ni tiles
// (lanes 0-15 -> tile 2*np {kgrp0,kgrp1}; lanes 16-31 -> tile 2*np+1).
// LDSM per warp k-tile: 16 + 8 = 24 (was 32) -> LSU issue floor 384 cyc/SMSP
// < ~485 cyc tensor -> tensor pipe becomes the binder.
// ---------------------------------------------------------------------------
#define BM 128
#define BN 256
#define KC 32
#define STAGES 3
#define STG_WORDS 12288
#define SMEM_BYTES (STAGES * STG_WORDS * 4)   // 147456

__global__ __launch_bounds__(512, 1) void gemm_tc(const float* __restrict__ Ag,
                                                  const float* __restrict__ Bg,
                                                  float* __restrict__ Dg,
                                                  int nk, int lda, int ldb, int ldd) {
    extern __shared__ uint32_t sm[];
    const uint32_t sbase = smem_u32(sm);
    const int tid  = threadIdx.x;
    const int lane = tid & 31;
    const int wid  = tid >> 5;
    const int wm   = (wid >> 3) * 64;   // 2 warps in M
    const int wn   = (wid & 7) * 32;    // 8 warps in N
    const int bm   = blockIdx.y * BM;
    const int bn   = blockIdx.x * BN;
    const int tig  = lane & 3;
    const int grp  = lane >> 2;

    // --- ldmatrix per-lane address precompute -----------------------------
    // A x4 (per mi): lane row = wm + mi*16 + (lane&15), kgrp flag = lane>>4.
    const int gflA = lane >> 4;
    uint32_t preA[4]; int rb7A[4];
    #pragma unroll
    for (int mi = 0; mi < 4; mi++) {
        int r = wm + mi * 16 + (lane & 15);
        preA[mi] = (uint32_t)(r * 128);
        rb7A[mi] = r & 7;
    }
    // B x4 (per ni-pair np): lanes 0-15 -> ni=2np, lanes 16-31 -> ni=2np+1;
    // row = wn + np*16 + ((lane>>4)&1)*8 + (lane&7); kgrp flag = (lane>>3)&1.
    const int gflB = (lane >> 3) & 1;
    uint32_t preB[2]; int rb7B[2];
    #pragma unroll
    for (int np = 0; np < 2; np++) {
        int r = wn + np * 16 + ((lane >> 4) << 3) + (lane & 7);
        preB[np] = (uint32_t)(r * 128);
        rb7B[np] = r & 7;
    }

    // Per-thread copy-slot geometry (16B chunks, 8 per 32-word row)
    auto issue_stage = [&](int stage, int k0) {
        const uint32_t abase = sbase + (uint32_t)stage * (STG_WORDS * 4);
        const uint32_t bbase = abase + 4096 * 4;
        #pragma unroll
        for (int i = 0; i < 2; i++) {
            int lin = tid + 512 * i;
            int r   = lin >> 3;
            int g   = lin & 7;
            uint32_t boff = (uint32_t)(r * 128 + ((g ^ (r & 7)) << 4));
            cp_async16(abase + boff, Ag + (size_t)(bm + r) * lda + k0 + g * 4);
        }
        #pragma unroll
        for (int i = 0; i < 4; i++) {
            int lin = tid + 512 * i;
            int r   = lin >> 3;
            int g   = lin & 7;
            uint32_t boff = (uint32_t)(r * 128 + ((g ^ (r & 7)) << 4));
            cp_async16(bbase + boff, Bg + (size_t)(bn + r) * ldb + k0 + g * 4);
        }
    };

    float acc[4][4][4];
    #pragma unroll
    for (int mi = 0; mi < 4; mi++)
        #pragma unroll
        for (int ni = 0; ni < 4; ni++)
            #pragma unroll
            for (int c = 0; c < 4; c++)
                acc[mi][ni][c] = 0.0f;

    // Prologue: stages 0..1
    issue_stage(0, 0);
    CP_ASYNC_COMMIT();
    issue_stage(1, KC);
    CP_ASYNC_COMMIT();

    int stage_rd = 0;
    int stage_wr = 2;
    for (int k = 0; k < nk; k++) {
        CP_ASYNC_WAIT_1();
        __syncthreads();

        // Issue tile k+2 into the buffer freed at iter k-1 (before MMA so the
        // LDGSTS latency is covered by this iteration's tensor work).
        if (k + STAGES - 1 < nk)
            issue_stage(stage_wr, (k + STAGES - 1) * KC);
        CP_ASYNC_COMMIT();

        const uint32_t astage = sbase + (uint32_t)stage_rd * (STG_WORDS * 4);
        const uint32_t bstage = astage + 4096 * 4;
        #pragma unroll
        for (int kk = 0; kk < 4; kk++) {
            uint32_t a[4][4];
            #pragma unroll
            for (int mi = 0; mi < 4; mi++) {
                uint32_t addr = astage + preA[mi] +
                                (uint32_t)((((2 * kk + gflA) ^ rb7A[mi])) << 4);
                ldsm_x4(a[mi], addr);
            }
            uint32_t b[4][2];
            #pragma unroll
            for (int np = 0; np < 2; np++) {
                uint32_t b4[4];
                uint32_t addr = bstage + preB[np] +
                                (uint32_t)((((2 * kk + gflB) ^ rb7B[np])) << 4);
                ldsm_x4(b4, addr);
                b[2 * np][0]     = b4[0];
                b[2 * np][1]     = b4[1];
                b[2 * np + 1][0] = b4[2];
                b[2 * np + 1][1] = b4[3];
            }
            #pragma unroll
            for (int mi = 0; mi < 4; mi++)
                #pragma unroll
                for (int ni = 0; ni < 4; ni++)
                    mma_tf32(acc[mi][ni], a[mi], b[ni]);
        }

        stage_rd = (stage_rd + 1 == STAGES) ? 0 : stage_rd + 1;
        stage_wr = (stage_wr + 1 == STAGES) ? 0 : stage_wr + 1;
    }

    // Epilogue: direct float2 stores (C fragment layout; 32B-sector aligned).
    #pragma unroll
    for (int mi = 0; mi < 4; mi++) {
        #pragma unroll
        for (int ni = 0; ni < 4; ni++) {
            const int r = bm + wm + mi * 16 + grp;
            const int c = bn + wn + ni * 8 + 2 * tig;
            float2 v0 = make_float2(acc[mi][ni][0], acc[mi][ni][1]);
            float2 v1 = make_float2(acc[mi][ni][2], acc[mi][ni][3]);
            *(float2*)&Dg[(size_t)r       * ldd + c] = v0;
            *(float2*)&Dg[(size_t)(r + 8) * ldd + c] = v1;
        }
    }
}

// ---------------------------------------------------------------------------
// Elementwise tf32 convert: dst[i] = tf32_rna(src[i])
// ---------------------------------------------------------------------------
__global__ __launch_bounds__(256) void cvt_copy(const float* __restrict__ src,
                                                float* __restrict__ dst) {
    const size_t i = ((size_t)blockIdx.x * 256 + threadIdx.x) * 4;
    float4 v = *(const float4*)(src + i);
    uint4 w;
    w.x = f2tf32(v.x); w.y = f2tf32(v.y);
    w.z = f2tf32(v.z); w.w = f2tf32(v.w);
    *(uint4*)(dst + i) = w;
}

// ---------------------------------------------------------------------------
// V transpose + tf32 convert: g_vt[e][p] = tf32(V[p][e])
// ---------------------------------------------------------------------------
__global__ __launch_bounds__(256) void transpose_v(const float* __restrict__ V) {
    __shared__ float t[32][33];
    const int bx = blockIdx.x * 32;  // E
    const int by = blockIdx.y * 32;  // P
    const int tx = threadIdx.x;
    const int ty = threadIdx.y;
    #pragma unroll
    for (int j = 0; j < 32; j += 8)
        t[ty + j][tx] = V[(size_t)(by + ty + j) * E_DIM + bx + tx];
    __syncthreads();
    #pragma unroll
    for (int j = 0; j < 32; j += 8)
        *(uint32_t*)&g_vt[(size_t)(bx + ty + j) * P_DIM + by + tx] =
            f2tf32(t[tx][ty + j]);
}

// ---------------------------------------------------------------------------
// Row softmax over P_DIM=4096, in place; 1/sqrt(E) folded in; output rounded
// to tf32 so the AV GEMM needs no conversion.
// ---------------------------------------------------------------------------
__global__ __launch_bounds__(256) void softmax_rows(float scale) {
    __shared__ float red[8];
    const int t    = threadIdx.x;
    const int lane = t & 31;
    const int w    = t >> 5;
    float4* sr = (float4*)(g_scores + (size_t)blockIdx.x * P_DIM);

    float4 v[4];
    float m = -3.0e38f;
    #pragma unroll
    for (int j = 0; j < 4; j++) {
        v[j] = sr[t + 256 * j];
        m = fmaxf(m, fmaxf(fmaxf(v[j].x, v[j].y), fmaxf(v[j].z, v[j].w)));
    }
    #pragma unroll
    for (int o = 16; o > 0; o >>= 1)
        m = fmaxf(m, __shfl_xor_sync(0xffffffffu, m, o));
    if (lane == 0) red[w] = m;
    __syncthreads();
    m = red[0];
    #pragma unroll
    for (int i = 1; i < 8; i++) m = fmaxf(m, red[i]);

    float s = 0.0f;
    #pragma unroll
    for (int j = 0; j < 4; j++) {
        v[j].x = __expf((v[j].x - m) * scale);
        v[j].y = __expf((v[j].y - m) * scale);
        v[j].z = __expf((v[j].z - m) * scale);
        v[j].w = __expf((v[j].w - m) * scale);
        s += v[j].x + v[j].y + v[j].z + v[j].w;
    }
    #pragma unroll
    for (int o = 16; o > 0; o >>= 1)
        s += __shfl_xor_sync(0xffffffffu, s, o);
    __syncthreads();
    if (lane == 0) red[w] = s;
    __syncthreads();
    s = 0.0f;
    #pragma unroll
    for (int i = 0; i < 8; i++) s += red[i];
    const float inv = 1.0f / s;

    #pragma unroll
    for (int j = 0; j < 4; j++) {
        uint4 o;
        o.x = f2tf32(v[j].x * inv);
        o.y = f2tf32(v[j].y * inv);
        o.z = f2tf32(v[j].z * inv);
        o.w = f2tf32(v[j].w * inv);
        *(uint4*)&sr[t + 256 * j] = o;
    }
}

// ---------------------------------------------------------------------------
// Launch. Inputs: x [4,2048,1024], K [4096,1024], V [4096,1024]; out fp32.
// Only kernel launches enqueued -> graph-capturable.
// ---------------------------------------------------------------------------
extern "C" void kernel_launch(void* const* d_in, const int* in_sizes, int n_in,
                              void* d_out, int out_size) {
    (void)in_sizes; (void)n_in; (void)out_size;
    const float* x  = (const float*)d_in[0];
    const float* Kw = (const float*)d_in[1];
    const float* V  = (const float*)d_in[2];
    float* out = (float*)d_out;

    cudaFuncSetAttribute(gemm_tc, cudaFuncAttributeMaxDynamicSharedMemorySize,
                         SMEM_BYTES);

    void *p_scores, *p_xt, *p_kt, *p_vt;
    cudaGetSymbolAddress(&p_scores, g_scores);
    cudaGetSymbolAddress(&p_xt, g_xt);
    cudaGetSymbolAddress(&p_kt, g_kt);
    cudaGetSymbolAddress(&p_vt, g_vt);
    float* scores = (float*)p_scores;
    float* xt = (float*)p_xt;
    float* kt = (float*)p_kt;
    float* vt = (float*)p_vt;

    // Pre-convert inputs to tf32 (once); transpose+convert V.
    cvt_copy<<<(M_TOTAL * E_DIM) / 1024, 256>>>(x, xt);
    cvt_copy<<<(P_DIM * E_DIM) / 1024, 256>>>(Kw, kt);
    transpose_v<<<dim3(E_DIM / 32, P_DIM / 32), dim3(32, 8)>>>(V);

    // raw scores = x @ K^T (scale folded into softmax)
    gemm_tc<<<dim3(P_DIM / BN, M_TOTAL / BM), 512, SMEM_BYTES>>>(
        xt, kt, scores, E_DIM / KC, E_DIM, E_DIM, P_DIM);

    softmax_rows<<<M_TOTAL, 256>>>(0.03125f);

    // out = attn @ V (B = V^T, K-major over P)
    gemm_tc<<<dim3(E_DIM / BN, M_TOTAL / BM), 512, SMEM_BYTES>>>(
        scores, vt, out, P_DIM / KC, P_DIM, P_DIM, E_DIM);
}

// round 11
// speedup vs baseline: 2.5172x; 1.0554x over previous
#include <cuda_runtime.h>
#include <stdint.h>

// ---------------------------------------------------------------------------
// Problem dims (fixed by the dataset)
// ---------------------------------------------------------------------------
#define M_TOTAL 8192   // B*S = 4*2048
#define E_DIM   1024
#define P_DIM   4096

// Device scratch (__device__ globals = sanctioned scratch)
__device__ float g_scores[(size_t)M_TOTAL * (size_t)P_DIM];  // 128 MB
__device__ float g_xt[(size_t)M_TOTAL * (size_t)E_DIM];      // 32 MB, tf32(x)
__device__ float g_kt[(size_t)P_DIM * (size_t)E_DIM];        // 16 MB, tf32(K)
__device__ float g_vt[(size_t)E_DIM * (size_t)P_DIM];        // 16 MB, tf32(V^T)

// ---------------------------------------------------------------------------
// Helpers
// ---------------------------------------------------------------------------
__device__ __forceinline__ uint32_t f2tf32(float x) {
    uint32_t r;
    asm("cvt.rna.tf32.f32 %0, %1;" : "=r"(r) : "f"(x));
    return r;
}

__device__ __forceinline__ uint32_t smem_u32(const void* p) {
    uint32_t a;
    asm("{ .reg .u64 t; cvta.to.shared.u64 t, %1; cvt.u32.u64 %0, t; }"
        : "=r"(a) : "l"(p));
    return a;
}

__device__ __forceinline__ void cp_async16(uint32_t dst, const void* src) {
    asm volatile("cp.async.cg.shared.global [%0], [%1], 16;"
                 :: "r"(dst), "l"(src) : "memory");
}
#define CP_ASYNC_COMMIT() asm volatile("cp.async.commit_group;" ::: "memory")
#define CP_ASYNC_WAIT_1() asm volatile("cp.async.wait_group 1;" ::: "memory")

// ldmatrix: for tf32 data each m8n8.b16 tile == 8 rows x 4 tf32; lane l gets
// element (row=l>>2, col=l&3) == the (grp,tig) fragment mapping of m16n8k8.
__device__ __forceinline__ void ldsm_x4(uint32_t r[4], uint32_t addr) {
    asm volatile("ldmatrix.sync.aligned.m8n8.x4.shared.b16 {%0,%1,%2,%3}, [%4];"
                 : "=r"(r[0]), "=r"(r[1]), "=r"(r[2]), "=r"(r[3]) : "r"(addr));
}

__device__ __forceinline__ void mma_tf32(float c[4], const uint32_t a[4], const uint32_t b[2]) {
    asm volatile(
        "mma.sync.aligned.m16n8k8.row.col.f32.tf32.tf32.f32 "
        "{%0,%1,%2,%3}, {%4,%5,%6,%7}, {%8,%9}, {%0,%1,%2,%3};"
        : "+f"(c[0]), "+f"(c[1]), "+f"(c[2]), "+f"(c[3])
        : "r"(a[0]), "r"(a[1]), "r"(a[2]), "r"(a[3]),
          "r"(b[0]), "r"(b[1]));
}

// ---------------------------------------------------------------------------
// GEMM: D[m,n] = sum_k A[m,k]*B[n,k]; A,B already tf32-rounded in gmem.
// CTA 128(M) x 128(N), KC=32, 256 threads = 8 warps (2x4), warp tile 64x32.
// TWO CTAs resident per SM (launch_bounds(256,2); smem 96KB/CTA): while one
// CTA's warps drain at its k-tile barrier / post-barrier LDSM ramp, the other
// CTA keeps the tensor pipe fed.
//
// cp.async 3-stage pipeline (next tile issued BEFORE the MMA phase).
// SMEM per stage: A 4096 words + B 4096 words (stage stride 8192 words).
// XOR swizzle in 32-word rows: word(r,c) -> r*32 + ((c>>2)^(r&7))*4 + (c&3)
// (byte addr: r*128 + ((g^(r&7))<<4)).
//  - cp.async 16B stores conflict-free; every ldmatrix phase reads 8 rows
//    with distinct (r&7) -> bank groups 4*(g^r) cover all 32 banks -> CF.
//
// A fragments: ldmatrix.x4 per mi (2 row-blocks x 2 k-groups).
// B fragments: ldmatrix.x4 PAIRED (one x4 covers two adjacent ni tiles:
// lanes 0-15 -> tile 2np, lanes 16-31 -> tile 2np+1).
// ---------------------------------------------------------------------------
#define BM 128
#define BN 128
#define KC 32
#define STAGES 3
#define STG_WORDS 8192
#define SMEM_BYTES (STAGES * STG_WORDS * 4)   // 98304 per CTA

__global__ __launch_bounds__(256, 2) void gemm_tc(const float* __restrict__ Ag,
                                                  const float* __restrict__ Bg,
                                                  float* __restrict__ Dg,
                                                  int nk, int lda, int ldb, int ldd) {
    extern __shared__ uint32_t sm[];
    const uint32_t sbase = smem_u32(sm);
    const int tid  = threadIdx.x;
    const int lane = tid & 31;
    const int wid  = tid >> 5;
    const int wm   = (wid >> 2) * 64;   // 2 warps in M
    const int wn   = (wid & 3) * 32;    // 4 warps in N
    const int bm   = blockIdx.y * BM;
    const int bn   = blockIdx.x * BN;
    const int tig  = lane & 3;
    const int grp  = lane >> 2;

    // --- ldmatrix per-lane address precompute -----------------------------
    // A x4 (per mi): lane row = wm + mi*16 + (lane&15), kgrp flag = lane>>4.
    const int gflA = lane >> 4;
    uint32_t preA[4]; int rb7A[4];
    #pragma unroll
    for (int mi = 0; mi < 4; mi++) {
        int r = wm + mi * 16 + (lane & 15);
        preA[mi] = (uint32_t)(r * 128);
        rb7A[mi] = r & 7;
    }
    // B x4 (per ni-pair np): lanes 0-15 -> ni=2np, lanes 16-31 -> ni=2np+1;
    // row = wn + np*16 + ((lane>>4)&1)*8 + (lane&7); kgrp flag = (lane>>3)&1.
    const int gflB = (lane >> 3) & 1;
    uint32_t preB[2]; int rb7B[2];
    #pragma unroll
    for (int np = 0; np < 2; np++) {
        int r = wn + np * 16 + ((lane >> 4) << 3) + (lane & 7);
        preB[np] = (uint32_t)(r * 128);
        rb7B[np] = r & 7;
    }

    // Per-thread copy-slot geometry (16B chunks, 8 per 32-word row):
    // A: 1024 chunks -> 4/thread; B: 1024 chunks -> 4/thread.
    auto issue_stage = [&](int stage, int k0) {
        const uint32_t abase = sbase + (uint32_t)stage * (STG_WORDS * 4);
        const uint32_t bbase = abase + 4096 * 4;
        #pragma unroll
        for (int i = 0; i < 4; i++) {
            int lin = tid + 256 * i;
            int r   = lin >> 3;
            int g   = lin & 7;
            uint32_t boff = (uint32_t)(r * 128 + ((g ^ (r & 7)) << 4));
            cp_async16(abase + boff, Ag + (size_t)(bm + r) * lda + k0 + g * 4);
        }
        #pragma unroll
        for (int i = 0; i < 4; i++) {
            int lin = tid + 256 * i;
            int r   = lin >> 3;
            int g   = lin & 7;
            uint32_t boff = (uint32_t)(r * 128 + ((g ^ (r & 7)) << 4));
            cp_async16(bbase + boff, Bg + (size_t)(bn + r) * ldb + k0 + g * 4);
        }
    };

    float acc[4][4][4];
    #pragma unroll
    for (int mi = 0; mi < 4; mi++)
        #pragma unroll
        for (int ni = 0; ni < 4; ni++)
            #pragma unroll
            for (int c = 0; c < 4; c++)
                acc[mi][ni][c] = 0.0f;

    // Prologue: stages 0..1
    issue_stage(0, 0);
    CP_ASYNC_COMMIT();
    issue_stage(1, KC);
    CP_ASYNC_COMMIT();

    int stage_rd = 0;
    int stage_wr = 2;
    for (int k = 0; k < nk; k++) {
        CP_ASYNC_WAIT_1();
        __syncthreads();

        // Issue tile k+2 into the buffer freed at iter k-1 (before MMA so the
        // LDGSTS latency is covered by this iteration's tensor work).
        if (k + STAGES - 1 < nk)
            issue_stage(stage_wr, (k + STAGES - 1) * KC);
        CP_ASYNC_COMMIT();

        const uint32_t astage = sbase + (uint32_t)stage_rd * (STG_WORDS * 4);
        const uint32_t bstage = astage + 4096 * 4;
        #pragma unroll
        for (int kk = 0; kk < 4; kk++) {
            uint32_t a[4][4];
            #pragma unroll
            for (int mi = 0; mi < 4; mi++) {
                uint32_t addr = astage + preA[mi] +
                                (uint32_t)((((2 * kk + gflA) ^ rb7A[mi])) << 4);
                ldsm_x4(a[mi], addr);
            }
            uint32_t b[4][2];
            #pragma unroll
            for (int np = 0; np < 2; np++) {
                uint32_t b4[4];
                uint32_t addr = bstage + preB[np] +
                                (uint32_t)((((2 * kk + gflB) ^ rb7B[np])) << 4);
                ldsm_x4(b4, addr);
                b[2 * np][0]     = b4[0];
                b[2 * np][1]     = b4[1];
                b[2 * np + 1][0] = b4[2];
                b[2 * np + 1][1] = b4[3];
            }
            #pragma unroll
            for (int mi = 0; mi < 4; mi++)
                #pragma unroll
                for (int ni = 0; ni < 4; ni++)
                    mma_tf32(acc[mi][ni], a[mi], b[ni]);
        }

        stage_rd = (stage_rd + 1 == STAGES) ? 0 : stage_rd + 1;
        stage_wr = (stage_wr + 1 == STAGES) ? 0 : stage_wr + 1;
    }

    // Epilogue: direct float2 stores (C fragment layout; 32B-sector aligned).
    #pragma unroll
    for (int mi = 0; mi < 4; mi++) {
        #pragma unroll
        for (int ni = 0; ni < 4; ni++) {
            const int r = bm + wm + mi * 16 + grp;
            const int c = bn + wn + ni * 8 + 2 * tig;
            float2 v0 = make_float2(acc[mi][ni][0], acc[mi][ni][1]);
            float2 v1 = make_float2(acc[mi][ni][2], acc[mi][ni][3]);
            *(float2*)&Dg[(size_t)r       * ldd + c] = v0;
            *(float2*)&Dg[(size_t)(r + 8) * ldd + c] = v1;
        }
    }
}

// ---------------------------------------------------------------------------
// Elementwise tf32 convert: dst[i] = tf32_rna(src[i])
// ---------------------------------------------------------------------------
__global__ __launch_bounds__(256) void cvt_copy(const float* __restrict__ src,
                                                float* __restrict__ dst) {
    const size_t i = ((size_t)blockIdx.x * 256 + threadIdx.x) * 4;
    float4 v = *(const float4*)(src + i);
    uint4 w;
    w.x = f2tf32(v.x); w.y = f2tf32(v.y);
    w.z = f2tf32(v.z); w.w = f2tf32(v.w);
    *(uint4*)(dst + i) = w;
}

// ---------------------------------------------------------------------------
// V transpose + tf32 convert: g_vt[e][p] = tf32(V[p][e])
// ---------------------------------------------------------------------------
__global__ __launch_bounds__(256) void transpose_v(const float* __restrict__ V) {
    __shared__ float t[32][33];
    const int bx = blockIdx.x * 32;  // E
    const int by = blockIdx.y * 32;  // P
    const int tx = threadIdx.x;
    const int ty = threadIdx.y;
    #pragma unroll
    for (int j = 0; j < 32; j += 8)
        t[ty + j][tx] = V[(size_t)(by + ty + j) * E_DIM + bx + tx];
    __syncthreads();
    #pragma unroll
    for (int j = 0; j < 32; j += 8)
        *(uint32_t*)&g_vt[(size_t)(bx + ty + j) * P_DIM + by + tx] =
            f2tf32(t[tx][ty + j]);
}

// ---------------------------------------------------------------------------
// Row softmax over P_DIM=4096, in place; 1/sqrt(E) folded in; output rounded
// to tf32 so the AV GEMM needs no conversion.
// ---------------------------------------------------------------------------
__global__ __launch_bounds__(256) void softmax_rows(float scale) {
    __shared__ float red[8];
    const int t    = threadIdx.x;
    const int lane = t & 31;
    const int w    = t >> 5;
    float4* sr = (float4*)(g_scores + (size_t)blockIdx.x * P_DIM);

    float4 v[4];
    float m = -3.0e38f;
    #pragma unroll
    for (int j = 0; j < 4; j++) {
        v[j] = sr[t + 256 * j];
        m = fmaxf(m, fmaxf(fmaxf(v[j].x, v[j].y), fmaxf(v[j].z, v[j].w)));
    }
    #pragma unroll
    for (int o = 16; o > 0; o >>= 1)
        m = fmaxf(m, __shfl_xor_sync(0xffffffffu, m, o));
    if (lane == 0) red[w] = m;
    __syncthreads();
    m = red[0];
    #pragma unroll
    for (int i = 1; i < 8; i++) m = fmaxf(m, red[i]);

    float s = 0.0f;
    #pragma unroll
    for (int j = 0; j < 4; j++) {
        v[j].x = __expf((v[j].x - m) * scale);
        v[j].y = __expf((v[j].y - m) * scale);
        v[j].z = __expf((v[j].z - m) * scale);
        v[j].w = __expf((v[j].w - m) * scale);
        s += v[j].x + v[j].y + v[j].z + v[j].w;
    }
    #pragma unroll
    for (int o = 16; o > 0; o >>= 1)
        s += __shfl_xor_sync(0xffffffffu, s, o);
    __syncthreads();
    if (lane == 0) red[w] = s;
    __syncthreads();
    s = 0.0f;
    #pragma unroll
    for (int i = 0; i < 8; i++) s += red[i];
    const float inv = 1.0f / s;

    #pragma unroll
    for (int j = 0; j < 4; j++) {
        uint4 o;
        o.x = f2tf32(v[j].x * inv);
        o.y = f2tf32(v[j].y * inv);
        o.z = f2tf32(v[j].z * inv);
        o.w = f2tf32(v[j].w * inv);
        *(uint4*)&sr[t + 256 * j] = o;
    }
}

// ---------------------------------------------------------------------------
// Launch. Inputs: x [4,2048,1024], K [4096,1024], V [4096,1024]; out fp32.
// Only kernel launches enqueued -> graph-capturable.
// ---------------------------------------------------------------------------
extern "C" void kernel_launch(void* const* d_in, const int* in_sizes, int n_in,
                              void* d_out, int out_size) {
    (void)in_sizes; (void)n_in; (void)out_size;
    const float* x  = (const float*)d_in[0];
    const float* Kw = (const float*)d_in[1];
    const float* V  = (const float*)d_in[2];
    float* out = (float*)d_out;

    cudaFuncSetAttribute(gemm_tc, cudaFuncAttributeMaxDynamicSharedMemorySize,
                         SMEM_BYTES);

    void *p_scores, *p_xt, *p_kt, *p_vt;
    cudaGetSymbolAddress(&p_scores, g_scores);
    cudaGetSymbolAddress(&p_xt, g_xt);
    cudaGetSymbolAddress(&p_kt, g_kt);
    cudaGetSymbolAddress(&p_vt, g_vt);
    float* scores = (float*)p_scores;
    float* xt = (float*)p_xt;
    float* kt = (float*)p_kt;
    float* vt = (float*)p_vt;

    // Pre-convert inputs to tf32 (once); transpose+convert V.
    cvt_copy<<<(M_TOTAL * E_DIM) / 1024, 256>>>(x, xt);
    cvt_copy<<<(P_DIM * E_DIM) / 1024, 256>>>(Kw, kt);
    transpose_v<<<dim3(E_DIM / 32, P_DIM / 32), dim3(32, 8)>>>(V);

    // raw scores = x @ K^T (scale folded into softmax)
    gemm_tc<<<dim3(P_DIM / BN, M_TOTAL / BM), 256, SMEM_BYTES>>>(
        xt, kt, scores, E_DIM / KC, E_DIM, E_DIM, P_DIM);

    softmax_rows<<<M_TOTAL, 256>>>(0.03125f);

    // out = attn @ V (B = V^T, K-major over P)
    gemm_tc<<<dim3(E_DIM / BN, M_TOTAL / BM), 256, SMEM_BYTES>>>(
        scores, vt, out, P_DIM / KC, P_DIM, P_DIM, E_DIM);
}

// round 12
// speedup vs baseline: 2.5281x; 1.0044x over previous
#include <cuda_runtime.h>
#include <stdint.h>

// ---------------------------------------------------------------------------
// Problem dims (fixed by the dataset)
// ---------------------------------------------------------------------------
#define M_TOTAL 8192   // B*S = 4*2048
#define E_DIM   1024
#define P_DIM   4096

// Device scratch (__device__ globals = sanctioned scratch)
__device__ float g_scores[(size_t)M_TOTAL * (size_t)P_DIM];  // 128 MB
__device__ float g_xt[(size_t)M_TOTAL * (size_t)E_DIM];      // 32 MB, tf32(x)
__device__ float g_kt[(size_t)P_DIM * (size_t)E_DIM];        // 16 MB, tf32(K)
__device__ float g_vt[(size_t)E_DIM * (size_t)P_DIM];        // 16 MB, tf32(V^T)

// ---------------------------------------------------------------------------
// Helpers
// ---------------------------------------------------------------------------
__device__ __forceinline__ uint32_t f2tf32(float x) {
    uint32_t r;
    asm("cvt.rna.tf32.f32 %0, %1;" : "=r"(r) : "f"(x));
    return r;
}

__device__ __forceinline__ uint32_t smem_u32(const void* p) {
    uint32_t a;
    asm("{ .reg .u64 t; cvta.to.shared.u64 t, %1; cvt.u32.u64 %0, t; }"
        : "=r"(a) : "l"(p));
    return a;
}

__device__ __forceinline__ void cp_async16(uint32_t dst, const void* src) {
    asm volatile("cp.async.cg.shared.global [%0], [%1], 16;"
                 :: "r"(dst), "l"(src) : "memory");
}
#define CP_ASYNC_COMMIT() asm volatile("cp.async.commit_group;" ::: "memory")
#define CP_ASYNC_WAIT_1() asm volatile("cp.async.wait_group 1;" ::: "memory")

// ldmatrix: for tf32 data each m8n8.b16 tile == 8 rows x 4 tf32; lane l gets
// element (row=l>>2, col=l&3) == the (grp,tig) fragment mapping of m16n8k8.
__device__ __forceinline__ void ldsm_x4(uint32_t r[4], uint32_t addr) {
    asm volatile("ldmatrix.sync.aligned.m8n8.x4.shared.b16 {%0,%1,%2,%3}, [%4];"
                 : "=r"(r[0]), "=r"(r[1]), "=r"(r[2]), "=r"(r[3]) : "r"(addr));
}

__device__ __forceinline__ void mma_tf32(float c[4], const uint32_t a[4], const uint32_t b[2]) {
    asm volatile(
        "mma.sync.aligned.m16n8k8.row.col.f32.tf32.tf32.f32 "
        "{%0,%1,%2,%3}, {%4,%5,%6,%7}, {%8,%9}, {%0,%1,%2,%3};"
        : "+f"(c[0]), "+f"(c[1]), "+f"(c[2]), "+f"(c[3])
        : "r"(a[0]), "r"(a[1]), "r"(a[2]), "r"(a[3]),
          "r"(b[0]), "r"(b[1]));
}

// ---------------------------------------------------------------------------
// GEMM: D[m,n] = sum_k A[m,k]*B[n,k]; A,B already tf32-rounded in gmem.
// CTA 128(M) x 128(N), KC=32, 256 threads = 8 warps (2x4), warp tile 64x32.
// TWO CTAs resident per SM (launch_bounds(256,2); 96KB smem, 128 regs = RF
// full): one CTA's MMA phase overlaps the other's barrier/ramp bubbles.
//
// cp.async 3-stage pipeline. The next stage's cp.asyncs are issued BETWEEN
// kk=0 and kk=1 so the post-barrier critical path is LDSM-only and the LSU
// burst lands while the tensor pipe is already fed.
//
// SMEM per stage: A 4096 words + B 4096 words (stage stride 8192 words).
// XOR swizzle in 32-word rows: word(r,c) -> r*32 + ((c>>2)^(r&7))*4 + (c&3)
// (byte addr: r*128 + ((g^(r&7))<<4)).
//  - cp.async 16B stores conflict-free; every ldmatrix phase reads 8 rows
//    with distinct (r&7) -> bank groups 4*(g^r) cover all 32 banks -> CF.
//
// A fragments: ldmatrix.x4 per mi (2 row-blocks x 2 k-groups).
// B fragments: ldmatrix.x4 PAIRED (one x4 covers two adjacent ni tiles:
// lanes 0-15 -> tile 2np, lanes 16-31 -> tile 2np+1).
// ---------------------------------------------------------------------------
#define BM 128
#define BN 128
#define KC 32
#define STAGES 3
#define STG_WORDS 8192
#define SMEM_BYTES (STAGES * STG_WORDS * 4)   // 98304 per CTA

__global__ __launch_bounds__(256, 2) void gemm_tc(const float* __restrict__ Ag,
                                                  const float* __restrict__ Bg,
                                                  float* __restrict__ Dg,
                                                  int nk, int lda, int ldb, int ldd) {
    extern __shared__ uint32_t sm[];
    const uint32_t sbase = smem_u32(sm);
    const int tid  = threadIdx.x;
    const int lane = tid & 31;
    const int wid  = tid >> 5;
    const int wm   = (wid >> 2) * 64;   // 2 warps in M
    const int wn   = (wid & 3) * 32;    // 4 warps in N
    const int bm   = blockIdx.y * BM;
    const int bn   = blockIdx.x * BN;
    const int tig  = lane & 3;
    const int grp  = lane >> 2;

    // --- ldmatrix per-lane address precompute -----------------------------
    // A x4 (per mi): lane row = wm + mi*16 + (lane&15), kgrp flag = lane>>4.
    const int gflA = lane >> 4;
    uint32_t preA[4]; int rb7A[4];
    #pragma unroll
    for (int mi = 0; mi < 4; mi++) {
        int r = wm + mi * 16 + (lane & 15);
        preA[mi] = (uint32_t)(r * 128);
        rb7A[mi] = r & 7;
    }
    // B x4 (per ni-pair np): lanes 0-15 -> ni=2np, lanes 16-31 -> ni=2np+1;
    // row = wn + np*16 + ((lane>>4)&1)*8 + (lane&7); kgrp flag = (lane>>3)&1.
    const int gflB = (lane >> 3) & 1;
    uint32_t preB[2]; int rb7B[2];
    #pragma unroll
    for (int np = 0; np < 2; np++) {
        int r = wn + np * 16 + ((lane >> 4) << 3) + (lane & 7);
        preB[np] = (uint32_t)(r * 128);
        rb7B[np] = r & 7;
    }

    // Per-thread copy-slot geometry (16B chunks, 8 per 32-word row):
    // A: 1024 chunks -> 4/thread; B: 1024 chunks -> 4/thread.
    auto issue_stage = [&](int stage, int k0) {
        const uint32_t abase = sbase + (uint32_t)stage * (STG_WORDS * 4);
        const uint32_t bbase = abase + 4096 * 4;
        #pragma unroll
        for (int i = 0; i < 4; i++) {
            int lin = tid + 256 * i;
            int r   = lin >> 3;
            int g   = lin & 7;
            uint32_t boff = (uint32_t)(r * 128 + ((g ^ (r & 7)) << 4));
            cp_async16(abase + boff, Ag + (size_t)(bm + r) * lda + k0 + g * 4);
        }
        #pragma unroll
        for (int i = 0; i < 4; i++) {
            int lin = tid + 256 * i;
            int r   = lin >> 3;
            int g   = lin & 7;
            uint32_t boff = (uint32_t)(r * 128 + ((g ^ (r & 7)) << 4));
            cp_async16(bbase + boff, Bg + (size_t)(bn + r) * ldb + k0 + g * 4);
        }
    };

    float acc[4][4][4];
    #pragma unroll
    for (int mi = 0; mi < 4; mi++)
        #pragma unroll
        for (int ni = 0; ni < 4; ni++)
            #pragma unroll
            for (int c = 0; c < 4; c++)
                acc[mi][ni][c] = 0.0f;

    // Prologue: stages 0..1
    issue_stage(0, 0);
    CP_ASYNC_COMMIT();
    issue_stage(1, KC);
    CP_ASYNC_COMMIT();

    int stage_rd = 0;
    int stage_wr = 2;
    for (int k = 0; k < nk; k++) {
        CP_ASYNC_WAIT_1();
        __syncthreads();

        const uint32_t astage = sbase + (uint32_t)stage_rd * (STG_WORDS * 4);
        const uint32_t bstage = astage + 4096 * 4;

        #pragma unroll
        for (int kk = 0; kk < 4; kk++) {
            // Fragments for this k-step (LDSM-only critical path at kk=0).
            uint32_t a[4][4];
            #pragma unroll
            for (int mi = 0; mi < 4; mi++) {
                uint32_t addr = astage + preA[mi] +
                                (uint32_t)((((2 * kk + gflA) ^ rb7A[mi])) << 4);
                ldsm_x4(a[mi], addr);
            }
            uint32_t b[4][2];
            {
                uint32_t b4[4];
                uint32_t addr0 = bstage + preB[0] +
                                 (uint32_t)((((2 * kk + gflB) ^ rb7B[0])) << 4);
                ldsm_x4(b4, addr0);
                b[0][0] = b4[0]; b[0][1] = b4[1];
                b[1][0] = b4[2]; b[1][1] = b4[3];
            }
            // First half of the MMAs (ni = 0,1) while B-pair-1 loads next.
            #pragma unroll
            for (int mi = 0; mi < 4; mi++) {
                mma_tf32(acc[mi][0], a[mi], b[0]);
                mma_tf32(acc[mi][1], a[mi], b[1]);
            }
            {
                uint32_t b4[4];
                uint32_t addr1 = bstage + preB[1] +
                                 (uint32_t)((((2 * kk + gflB) ^ rb7B[1])) << 4);
                ldsm_x4(b4, addr1);
                b[2][0] = b4[0]; b[2][1] = b4[1];
                b[3][0] = b4[2]; b[3][1] = b4[3];
            }
            #pragma unroll
            for (int mi = 0; mi < 4; mi++) {
                mma_tf32(acc[mi][2], a[mi], b[2]);
                mma_tf32(acc[mi][3], a[mi], b[3]);
            }

            // Issue the next stage's copies AFTER the first k-step: tensor
            // pipe is already busy, LSU burst is off the critical path.
            if (kk == 0) {
                if (k + STAGES - 1 < nk)
                    issue_stage(stage_wr, (k + STAGES - 1) * KC);
                CP_ASYNC_COMMIT();
            }
        }

        stage_rd = (stage_rd + 1 == STAGES) ? 0 : stage_rd + 1;
        stage_wr = (stage_wr + 1 == STAGES) ? 0 : stage_wr + 1;
    }

    // Epilogue: direct float2 stores (C fragment layout; 32B-sector aligned).
    #pragma unroll
    for (int mi = 0; mi < 4; mi++) {
        #pragma unroll
        for (int ni = 0; ni < 4; ni++) {
            const int r = bm + wm + mi * 16 + grp;
            const int c = bn + wn + ni * 8 + 2 * tig;
            float2 v0 = make_float2(acc[mi][ni][0], acc[mi][ni][1]);
            float2 v1 = make_float2(acc[mi][ni][2], acc[mi][ni][3]);
            *(float2*)&Dg[(size_t)r       * ldd + c] = v0;
            *(float2*)&Dg[(size_t)(r + 8) * ldd + c] = v1;
        }
    }
}

// ---------------------------------------------------------------------------
// Elementwise tf32 convert for x and K in ONE launch:
//   i < NX       -> g_xt[i]       = tf32(x[i])
//   i >= NX      -> g_kt[i - NX]  = tf32(K[i - NX])
// ---------------------------------------------------------------------------
#define NX ((size_t)M_TOTAL * E_DIM)
#define NK ((size_t)P_DIM * E_DIM)
__global__ __launch_bounds__(256) void cvt_inputs(const float* __restrict__ x,
                                                  const float* __restrict__ Kw,
                                                  float* __restrict__ xt,
                                                  float* __restrict__ kt) {
    const size_t i = ((size_t)blockIdx.x * 256 + threadIdx.x) * 4;
    const float* src;
    float* dst;
    size_t off;
    if (i < NX) { src = x;  dst = xt; off = i; }
    else        { src = Kw; dst = kt; off = i - NX; }
    float4 v = *(const float4*)(src + off);
    uint4 w;
    w.x = f2tf32(v.x); w.y = f2tf32(v.y);
    w.z = f2tf32(v.z); w.w = f2tf32(v.w);
    *(uint4*)(dst + off) = w;
}

// ---------------------------------------------------------------------------
// V transpose + tf32 convert: g_vt[e][p] = tf32(V[p][e])
// ---------------------------------------------------------------------------
__global__ __launch_bounds__(256) void transpose_v(const float* __restrict__ V) {
    __shared__ float t[32][33];
    const int bx = blockIdx.x * 32;  // E
    const int by = blockIdx.y * 32;  // P
    const int tx = threadIdx.x;
    const int ty = threadIdx.y;
    #pragma unroll
    for (int j = 0; j < 32; j += 8)
        t[ty + j][tx] = V[(size_t)(by + ty + j) * E_DIM + bx + tx];
    __syncthreads();
    #pragma unroll
    for (int j = 0; j < 32; j += 8)
        *(uint32_t*)&g_vt[(size_t)(bx + ty + j) * P_DIM + by + tx] =
            f2tf32(t[tx][ty + j]);
}

// ---------------------------------------------------------------------------
// Row softmax over P_DIM=4096, in place; 1/sqrt(E) folded in; output rounded
// to tf32 so the AV GEMM needs no conversion.
// ---------------------------------------------------------------------------
__global__ __launch_bounds__(256) void softmax_rows(float scale) {
    __shared__ float red[8];
    const int t    = threadIdx.x;
    const int lane = t & 31;
    const int w    = t >> 5;
    float4* sr = (float4*)(g_scores + (size_t)blockIdx.x * P_DIM);

    float4 v[4];
    float m = -3.0e38f;
    #pragma unroll
    for (int j = 0; j < 4; j++) {
        v[j] = sr[t + 256 * j];
        m = fmaxf(m, fmaxf(fmaxf(v[j].x, v[j].y), fmaxf(v[j].z, v[j].w)));
    }
    #pragma unroll
    for (int o = 16; o > 0; o >>= 1)
        m = fmaxf(m, __shfl_xor_sync(0xffffffffu, m, o));
    if (lane == 0) red[w] = m;
    __syncthreads();
    m = red[0];
    #pragma unroll
    for (int i = 1; i < 8; i++) m = fmaxf(m, red[i]);

    float s = 0.0f;
    #pragma unroll
    for (int j = 0; j < 4; j++) {
        v[j].x = __expf((v[j].x - m) * scale);
        v[j].y = __expf((v[j].y - m) * scale);
        v[j].z = __expf((v[j].z - m) * scale);
        v[j].w = __expf((v[j].w - m) * scale);
        s += v[j].x + v[j].y + v[j].z + v[j].w;
    }
    #pragma unroll
    for (int o = 16; o > 0; o >>= 1)
        s += __shfl_xor_sync(0xffffffffu, s, o);
    __syncthreads();
    if (lane == 0) red[w] = s;
    __syncthreads();
    s = 0.0f;
    #pragma unroll
    for (int i = 0; i < 8; i++) s += red[i];
    const float inv = 1.0f / s;

    #pragma unroll
    for (int j = 0; j < 4; j++) {
        uint4 o;
        o.x = f2tf32(v[j].x * inv);
        o.y = f2tf32(v[j].y * inv);
        o.z = f2tf32(v[j].z * inv);
        o.w = f2tf32(v[j].w * inv);
        *(uint4*)&sr[t + 256 * j] = o;
    }
}

// ---------------------------------------------------------------------------
// Launch. Inputs: x [4,2048,1024], K [4096,1024], V [4096,1024]; out fp32.
// Only kernel launches enqueued -> graph-capturable.
// ---------------------------------------------------------------------------
extern "C" void kernel_launch(void* const* d_in, const int* in_sizes, int n_in,
                              void* d_out, int out_size) {
    (void)in_sizes; (void)n_in; (void)out_size;
    const float* x  = (const float*)d_in[0];
    const float* Kw = (const float*)d_in[1];
    const float* V  = (const float*)d_in[2];
    float* out = (float*)d_out;

    cudaFuncSetAttribute(gemm_tc, cudaFuncAttributeMaxDynamicSharedMemorySize,
                         SMEM_BYTES);

    void *p_scores, *p_xt, *p_kt, *p_vt;
    cudaGetSymbolAddress(&p_scores, g_scores);
    cudaGetSymbolAddress(&p_xt, g_xt);
    cudaGetSymbolAddress(&p_kt, g_kt);
    cudaGetSymbolAddress(&p_vt, g_vt);
    float* scores = (float*)p_scores;
    float* xt = (float*)p_xt;
    float* kt = (float*)p_kt;
    float* vt = (float*)p_vt;

    // Pre-convert inputs to tf32 (one fused launch); transpose+convert V.
    cvt_inputs<<<(unsigned)((NX + NK) / 1024), 256>>>(x, Kw, xt, kt);
    transpose_v<<<dim3(E_DIM / 32, P_DIM / 32), dim3(32, 8)>>>(V);

    // raw scores = x @ K^T (scale folded into softmax)
    gemm_tc<<<dim3(P_DIM / BN, M_TOTAL / BM), 256, SMEM_BYTES>>>(
        xt, kt, scores, E_DIM / KC, E_DIM, E_DIM, P_DIM);

    softmax_rows<<<M_TOTAL, 256>>>(0.03125f);

    // out = attn @ V (B = V^T, K-major over P)
    gemm_tc<<<dim3(E_DIM / BN, M_TOTAL / BM), 256, SMEM_BYTES>>>(
        scores, vt, out, P_DIM / KC, P_DIM, P_DIM, E_DIM);
}

// round 13
// speedup vs baseline: 3.3656x; 1.3313x over previous
#include <cuda_runtime.h>
#include <cuda_fp16.h>
#include <stdint.h>

// ---------------------------------------------------------------------------
// Problem dims (fixed by the dataset)
// ---------------------------------------------------------------------------
#define M_TOTAL 8192   // B*S = 4*2048
#define E_DIM   1024
#define P_DIM   4096

// Device scratch (__device__ globals = sanctioned scratch)
__device__ float  g_scores[(size_t)M_TOTAL * (size_t)P_DIM]; // 128 MB fp32 scores
__device__ __half g_attn[(size_t)M_TOTAL * (size_t)P_DIM];   // 64 MB fp16 attn
__device__ float  g_xt[(size_t)M_TOTAL * (size_t)E_DIM];     // 32 MB tf32(x)
__device__ float  g_kt[(size_t)P_DIM * (size_t)E_DIM];       // 16 MB tf32(K)
__device__ __half g_vth[(size_t)E_DIM * (size_t)P_DIM];      // 8 MB fp16(V^T)

// ---------------------------------------------------------------------------
// Helpers
// ---------------------------------------------------------------------------
__device__ __forceinline__ uint32_t f2tf32(float x) {
    uint32_t r;
    asm("cvt.rna.tf32.f32 %0, %1;" : "=r"(r) : "f"(x));
    return r;
}

__device__ __forceinline__ uint32_t smem_u32(const void* p) {
    uint32_t a;
    asm("{ .reg .u64 t; cvta.to.shared.u64 t, %1; cvt.u32.u64 %0, t; }"
        : "=r"(a) : "l"(p));
    return a;
}

__device__ __forceinline__ void cp_async16(uint32_t dst, const void* src) {
    asm volatile("cp.async.cg.shared.global [%0], [%1], 16;"
                 :: "r"(dst), "l"(src) : "memory");
}
#define CP_ASYNC_COMMIT() asm volatile("cp.async.commit_group;" ::: "memory")
#define CP_ASYNC_WAIT_1() asm volatile("cp.async.wait_group 1;" ::: "memory")

__device__ __forceinline__ void ldsm_x4(uint32_t r[4], uint32_t addr) {
    asm volatile("ldmatrix.sync.aligned.m8n8.x4.shared.b16 {%0,%1,%2,%3}, [%4];"
                 : "=r"(r[0]), "=r"(r[1]), "=r"(r[2]), "=r"(r[3]) : "r"(addr));
}

__device__ __forceinline__ void mma_tf32(float c[4], const uint32_t a[4], const uint32_t b[2]) {
    asm volatile(
        "mma.sync.aligned.m16n8k8.row.col.f32.tf32.tf32.f32 "
        "{%0,%1,%2,%3}, {%4,%5,%6,%7}, {%8,%9}, {%0,%1,%2,%3};"
        : "+f"(c[0]), "+f"(c[1]), "+f"(c[2]), "+f"(c[3])
        : "r"(a[0]), "r"(a[1]), "r"(a[2]), "r"(a[3]),
          "r"(b[0]), "r"(b[1]));
}

__device__ __forceinline__ void mma_f16(float c[4], const uint32_t a[4], const uint32_t b[2]) {
    asm volatile(
        "mma.sync.aligned.m16n8k16.row.col.f32.f16.f16.f32 "
        "{%0,%1,%2,%3}, {%4,%5,%6,%7}, {%8,%9}, {%0,%1,%2,%3};"
        : "+f"(c[0]), "+f"(c[1]), "+f"(c[2]), "+f"(c[3])
        : "r"(a[0]), "r"(a[1]), "r"(a[2]), "r"(a[3]),
          "r"(b[0]), "r"(b[1]));
}

// ---------------------------------------------------------------------------
// Shared tiling constants. Both GEMMs: CTA 128x128, 256 thr (8 warps, 2x4),
// warp tile 64x32, 3-stage cp.async, 2 CTAs/SM, 32KB smem/stage (96KB/CTA).
// Rows are always 128 BYTES (32 tf32 or 64 fp16), XOR-swizzled in 16B groups:
//   byte(r, g) -> r*128 + ((g ^ (r&7)) << 4)
// cp.async 16B stores and every ldmatrix phase are bank-conflict-free.
// ---------------------------------------------------------------------------
#define BM 128
#define BN 128
#define STAGES 3
#define STG_WORDS 8192                        // 32KB per stage (A 16KB + B 16KB)
#define SMEM_BYTES (STAGES * STG_WORDS * 4)   // 98304 per CTA

// ---------------------------------------------------------------------------
// TF32 GEMM (QK^T): D[m,n] = sum_k A[m,k]*B[n,k], KC=32 floats per tile.
// ---------------------------------------------------------------------------
#define KC32 32

__global__ __launch_bounds__(256, 2) void gemm_tc(const float* __restrict__ Ag,
                                                  const float* __restrict__ Bg,
                                                  float* __restrict__ Dg,
                                                  int nk, int lda, int ldb, int ldd) {
    extern __shared__ uint32_t sm[];
    const uint32_t sbase = smem_u32(sm);
    const int tid  = threadIdx.x;
    const int lane = tid & 31;
    const int wid  = tid >> 5;
    const int wm   = (wid >> 2) * 64;
    const int wn   = (wid & 3) * 32;
    const int bm   = blockIdx.y * BM;
    const int bn   = blockIdx.x * BN;
    const int tig  = lane & 3;
    const int grp  = lane >> 2;

    const int gflA = lane >> 4;
    uint32_t preA[4]; int rb7A[4];
    #pragma unroll
    for (int mi = 0; mi < 4; mi++) {
        int r = wm + mi * 16 + (lane & 15);
        preA[mi] = (uint32_t)(r * 128);
        rb7A[mi] = r & 7;
    }
    const int gflB = (lane >> 3) & 1;
    uint32_t preB[2]; int rb7B[2];
    #pragma unroll
    for (int np = 0; np < 2; np++) {
        int r = wn + np * 16 + ((lane >> 4) << 3) + (lane & 7);
        preB[np] = (uint32_t)(r * 128);
        rb7B[np] = r & 7;
    }

    auto issue_stage = [&](int stage, int k0) {
        const uint32_t abase = sbase + (uint32_t)stage * (STG_WORDS * 4);
        const uint32_t bbase = abase + 4096 * 4;
        #pragma unroll
        for (int i = 0; i < 4; i++) {
            int lin = tid + 256 * i;
            int r   = lin >> 3;
            int g   = lin & 7;
            uint32_t boff = (uint32_t)(r * 128 + ((g ^ (r & 7)) << 4));
            cp_async16(abase + boff, Ag + (size_t)(bm + r) * lda + k0 + g * 4);
        }
        #pragma unroll
        for (int i = 0; i < 4; i++) {
            int lin = tid + 256 * i;
            int r   = lin >> 3;
            int g   = lin & 7;
            uint32_t boff = (uint32_t)(r * 128 + ((g ^ (r & 7)) << 4));
            cp_async16(bbase + boff, Bg + (size_t)(bn + r) * ldb + k0 + g * 4);
        }
    };

    float acc[4][4][4];
    #pragma unroll
    for (int mi = 0; mi < 4; mi++)
        #pragma unroll
        for (int ni = 0; ni < 4; ni++)
            #pragma unroll
            for (int c = 0; c < 4; c++)
                acc[mi][ni][c] = 0.0f;

    issue_stage(0, 0);
    CP_ASYNC_COMMIT();
    issue_stage(1, KC32);
    CP_ASYNC_COMMIT();

    int stage_rd = 0;
    int stage_wr = 2;
    for (int k = 0; k < nk; k++) {
        CP_ASYNC_WAIT_1();
        __syncthreads();

        const uint32_t astage = sbase + (uint32_t)stage_rd * (STG_WORDS * 4);
        const uint32_t bstage = astage + 4096 * 4;

        #pragma unroll
        for (int kk = 0; kk < 4; kk++) {
            uint32_t a[4][4];
            #pragma unroll
            for (int mi = 0; mi < 4; mi++) {
                uint32_t addr = astage + preA[mi] +
                                (uint32_t)((((2 * kk + gflA) ^ rb7A[mi])) << 4);
                ldsm_x4(a[mi], addr);
            }
            uint32_t b[4][2];
            {
                uint32_t b4[4];
                uint32_t addr0 = bstage + preB[0] +
                                 (uint32_t)((((2 * kk + gflB) ^ rb7B[0])) << 4);
                ldsm_x4(b4, addr0);
                b[0][0] = b4[0]; b[0][1] = b4[1];
                b[1][0] = b4[2]; b[1][1] = b4[3];
            }
            #pragma unroll
            for (int mi = 0; mi < 4; mi++) {
                mma_tf32(acc[mi][0], a[mi], b[0]);
                mma_tf32(acc[mi][1], a[mi], b[1]);
            }
            {
                uint32_t b4[4];
                uint32_t addr1 = bstage + preB[1] +
                                 (uint32_t)((((2 * kk + gflB) ^ rb7B[1])) << 4);
                ldsm_x4(b4, addr1);
                b[2][0] = b4[0]; b[2][1] = b4[1];
                b[3][0] = b4[2]; b[3][1] = b4[3];
            }
            #pragma unroll
            for (int mi = 0; mi < 4; mi++) {
                mma_tf32(acc[mi][2], a[mi], b[2]);
                mma_tf32(acc[mi][3], a[mi], b[3]);
            }
            if (kk == 0) {
                if (k + STAGES - 1 < nk)
                    issue_stage(stage_wr, (k + STAGES - 1) * KC32);
                CP_ASYNC_COMMIT();
            }
        }

        stage_rd = (stage_rd + 1 == STAGES) ? 0 : stage_rd + 1;
        stage_wr = (stage_wr + 1 == STAGES) ? 0 : stage_wr + 1;
    }

    #pragma unroll
    for (int mi = 0; mi < 4; mi++) {
        #pragma unroll
        for (int ni = 0; ni < 4; ni++) {
            const int r = bm + wm + mi * 16 + grp;
            const int c = bn + wn + ni * 8 + 2 * tig;
            float2 v0 = make_float2(acc[mi][ni][0], acc[mi][ni][1]);
            float2 v1 = make_float2(acc[mi][ni][2], acc[mi][ni][3]);
            *(float2*)&Dg[(size_t)r       * ldd + c] = v0;
            *(float2*)&Dg[(size_t)(r + 8) * ldd + c] = v1;
        }
    }
}

// ---------------------------------------------------------------------------
// FP16 GEMM (attn @ V): D[m,n] = sum_k A[m,k]*B[n,k], fp16 in, fp32 accum.
// KC=64 halves per tile (same 128-byte rows); mma m16n8k16 -> 4 k-steps and
// the SAME ldmatrix/fragment geometry as the tf32 kernel (16B-group iso).
// ---------------------------------------------------------------------------
#define KC64 64

__global__ __launch_bounds__(256, 2) void gemm_hc(const __half* __restrict__ Ag,
                                                  const __half* __restrict__ Bg,
                                                  float* __restrict__ Dg,
                                                  int nk, int lda, int ldb, int ldd) {
    extern __shared__ uint32_t sm[];
    const uint32_t sbase = smem_u32(sm);
    const int tid  = threadIdx.x;
    const int lane = tid & 31;
    const int wid  = tid >> 5;
    const int wm   = (wid >> 2) * 64;
    const int wn   = (wid & 3) * 32;
    const int bm   = blockIdx.y * BM;
    const int bn   = blockIdx.x * BN;
    const int tig  = lane & 3;
    const int grp  = lane >> 2;

    const int gflA = lane >> 4;          // k-half flag for A (matrices 2,3)
    uint32_t preA[4]; int rb7A[4];
    #pragma unroll
    for (int mi = 0; mi < 4; mi++) {
        int r = wm + mi * 16 + (lane & 15);
        preA[mi] = (uint32_t)(r * 128);
        rb7A[mi] = r & 7;
    }
    const int gflB = (lane >> 3) & 1;    // k-half flag for B
    uint32_t preB[2]; int rb7B[2];
    #pragma unroll
    for (int np = 0; np < 2; np++) {
        int r = wn + np * 16 + ((lane >> 4) << 3) + (lane & 7);
        preB[np] = (uint32_t)(r * 128);
        rb7B[np] = r & 7;
    }

    // A: 128 rows x 128B -> 1024 chunks -> 4/thread; B same.
    auto issue_stage = [&](int stage, int k0) {
        const uint32_t abase = sbase + (uint32_t)stage * (STG_WORDS * 4);
        const uint32_t bbase = abase + 4096 * 4;
        #pragma unroll
        for (int i = 0; i < 4; i++) {
            int lin = tid + 256 * i;
            int r   = lin >> 3;
            int g   = lin & 7;
            uint32_t boff = (uint32_t)(r * 128 + ((g ^ (r & 7)) << 4));
            cp_async16(abase + boff, Ag + (size_t)(bm + r) * lda + k0 + g * 8);
        }
        #pragma unroll
        for (int i = 0; i < 4; i++) {
            int lin = tid + 256 * i;
            int r   = lin >> 3;
            int g   = lin & 7;
            uint32_t boff = (uint32_t)(r * 128 + ((g ^ (r & 7)) << 4));
            cp_async16(bbase + boff, Bg + (size_t)(bn + r) * ldb + k0 + g * 8);
        }
    };

    float acc[4][4][4];
    #pragma unroll
    for (int mi = 0; mi < 4; mi++)
        #pragma unroll
        for (int ni = 0; ni < 4; ni++)
            #pragma unroll
            for (int c = 0; c < 4; c++)
                acc[mi][ni][c] = 0.0f;

    issue_stage(0, 0);
    CP_ASYNC_COMMIT();
    issue_stage(1, KC64);
    CP_ASYNC_COMMIT();

    int stage_rd = 0;
    int stage_wr = 2;
    for (int k = 0; k < nk; k++) {
        CP_ASYNC_WAIT_1();
        __syncthreads();

        const uint32_t astage = sbase + (uint32_t)stage_rd * (STG_WORDS * 4);
        const uint32_t bstage = astage + 4096 * 4;

        #pragma unroll
        for (int kk = 0; kk < 4; kk++) {   // 4 x k16 steps over KC64
            uint32_t a[4][4];
            #pragma unroll
            for (int mi = 0; mi < 4; mi++) {
                uint32_t addr = astage + preA[mi] +
                                (uint32_t)((((2 * kk + gflA) ^ rb7A[mi])) << 4);
                ldsm_x4(a[mi], addr);
            }
            uint32_t b[4][2];
            {
                uint32_t b4[4];
                uint32_t addr0 = bstage + preB[0] +
                                 (uint32_t)((((2 * kk + gflB) ^ rb7B[0])) << 4);
                ldsm_x4(b4, addr0);
                b[0][0] = b4[0]; b[0][1] = b4[1];
                b[1][0] = b4[2]; b[1][1] = b4[3];
            }
            #pragma unroll
            for (int mi = 0; mi < 4; mi++) {
                mma_f16(acc[mi][0], a[mi], b[0]);
                mma_f16(acc[mi][1], a[mi], b[1]);
            }
            {
                uint32_t b4[4];
                uint32_t addr1 = bstage + preB[1] +
                                 (uint32_t)((((2 * kk + gflB) ^ rb7B[1])) << 4);
                ldsm_x4(b4, addr1);
                b[2][0] = b4[0]; b[2][1] = b4[1];
                b[3][0] = b4[2]; b[3][1] = b4[3];
            }
            #pragma unroll
            for (int mi = 0; mi < 4; mi++) {
                mma_f16(acc[mi][2], a[mi], b[2]);
                mma_f16(acc[mi][3], a[mi], b[3]);
            }
            if (kk == 0) {
                if (k + STAGES - 1 < nk)
                    issue_stage(stage_wr, (k + STAGES - 1) * KC64);
                CP_ASYNC_COMMIT();
            }
        }

        stage_rd = (stage_rd + 1 == STAGES) ? 0 : stage_rd + 1;
        stage_wr = (stage_wr + 1 == STAGES) ? 0 : stage_wr + 1;
    }

    #pragma unroll
    for (int mi = 0; mi < 4; mi++) {
        #pragma unroll
        for (int ni = 0; ni < 4; ni++) {
            const int r = bm + wm + mi * 16 + grp;
            const int c = bn + wn + ni * 8 + 2 * tig;
            float2 v0 = make_float2(acc[mi][ni][0], acc[mi][ni][1]);
            float2 v1 = make_float2(acc[mi][ni][2], acc[mi][ni][3]);
            *(float2*)&Dg[(size_t)r       * ldd + c] = v0;
            *(float2*)&Dg[(size_t)(r + 8) * ldd + c] = v1;
        }
    }
}

// ---------------------------------------------------------------------------
// Elementwise tf32 convert for x and K in ONE launch.
// ---------------------------------------------------------------------------
#define NX ((size_t)M_TOTAL * E_DIM)
#define NK ((size_t)P_DIM * E_DIM)
__global__ __launch_bounds__(256) void cvt_inputs(const float* __restrict__ x,
                                                  const float* __restrict__ Kw,
                                                  float* __restrict__ xt,
                                                  float* __restrict__ kt) {
    const size_t i = ((size_t)blockIdx.x * 256 + threadIdx.x) * 4;
    const float* src;
    float* dst;
    size_t off;
    if (i < NX) { src = x;  dst = xt; off = i; }
    else        { src = Kw; dst = kt; off = i - NX; }
    float4 v = *(const float4*)(src + off);
    uint4 w;
    w.x = f2tf32(v.x); w.y = f2tf32(v.y);
    w.z = f2tf32(v.z); w.w = f2tf32(v.w);
    *(uint4*)(dst + off) = w;
}

// ---------------------------------------------------------------------------
// V transpose + fp16 convert: g_vth[e][p] = fp16(V[p][e])
// ---------------------------------------------------------------------------
__global__ __launch_bounds__(256) void transpose_v(const float* __restrict__ V) {
    __shared__ float t[32][33];
    const int bx = blockIdx.x * 32;  // E
    const int by = blockIdx.y * 32;  // P
    const int tx = threadIdx.x;
    const int ty = threadIdx.y;
    #pragma unroll
    for (int j = 0; j < 32; j += 8)
        t[ty + j][tx] = V[(size_t)(by + ty + j) * E_DIM + bx + tx];
    __syncthreads();
    #pragma unroll
    for (int j = 0; j < 32; j += 8)
        g_vth[(size_t)(bx + ty + j) * P_DIM + by + tx] =
            __float2half_rn(t[tx][ty + j]);
}

// ---------------------------------------------------------------------------
// Row softmax over P_DIM=4096: reads fp32 scores, writes fp16 attn.
// 1/sqrt(E) scale folded in.
// ---------------------------------------------------------------------------
__global__ __launch_bounds__(256) void softmax_rows(float scale) {
    __shared__ float red[8];
    const int t    = threadIdx.x;
    const int lane = t & 31;
    const int w    = t >> 5;
    const float4* sr = (const float4*)(g_scores + (size_t)blockIdx.x * P_DIM);
    uint2* ah = (uint2*)(g_attn + (size_t)blockIdx.x * P_DIM);

    float4 v[4];
    float m = -3.0e38f;
    #pragma unroll
    for (int j = 0; j < 4; j++) {
        v[j] = sr[t + 256 * j];
        m = fmaxf(m, fmaxf(fmaxf(v[j].x, v[j].y), fmaxf(v[j].z, v[j].w)));
    }
    #pragma unroll
    for (int o = 16; o > 0; o >>= 1)
        m = fmaxf(m, __shfl_xor_sync(0xffffffffu, m, o));
    if (lane == 0) red[w] = m;
    __syncthreads();
    m = red[0];
    #pragma unroll
    for (int i = 1; i < 8; i++) m = fmaxf(m, red[i]);

    float s = 0.0f;
    #pragma unroll
    for (int j = 0; j < 4; j++) {
        v[j].x = __expf((v[j].x - m) * scale);
        v[j].y = __expf((v[j].y - m) * scale);
        v[j].z = __expf((v[j].z - m) * scale);
        v[j].w = __expf((v[j].w - m) * scale);
        s += v[j].x + v[j].y + v[j].z + v[j].w;
    }
    #pragma unroll
    for (int o = 16; o > 0; o >>= 1)
        s += __shfl_xor_sync(0xffffffffu, s, o);
    __syncthreads();
    if (lane == 0) red[w] = s;
    __syncthreads();
    s = 0.0f;
    #pragma unroll
    for (int i = 0; i < 8; i++) s += red[i];
    const float inv = 1.0f / s;

    #pragma unroll
    for (int j = 0; j < 4; j++) {
        __half2 lo = __floats2half2_rn(v[j].x * inv, v[j].y * inv);
        __half2 hi = __floats2half2_rn(v[j].z * inv, v[j].w * inv);
        uint2 o;
        o.x = *(uint32_t*)&lo;
        o.y = *(uint32_t*)&hi;
        ah[t + 256 * j] = o;
    }
}

// ---------------------------------------------------------------------------
// Launch. Inputs: x [4,2048,1024], K [4096,1024], V [4096,1024]; out fp32.
// Only kernel launches enqueued -> graph-capturable.
// ---------------------------------------------------------------------------
extern "C" void kernel_launch(void* const* d_in, const int* in_sizes, int n_in,
                              void* d_out, int out_size) {
    (void)in_sizes; (void)n_in; (void)out_size;
    const float* x  = (const float*)d_in[0];
    const float* Kw = (const float*)d_in[1];
    const float* V  = (const float*)d_in[2];
    float* out = (float*)d_out;

    cudaFuncSetAttribute(gemm_tc, cudaFuncAttributeMaxDynamicSharedMemorySize,
                         SMEM_BYTES);
    cudaFuncSetAttribute(gemm_hc, cudaFuncAttributeMaxDynamicSharedMemorySize,
                         SMEM_BYTES);

    void *p_scores, *p_attn, *p_xt, *p_kt, *p_vth;
    cudaGetSymbolAddress(&p_scores, g_scores);
    cudaGetSymbolAddress(&p_attn, g_attn);
    cudaGetSymbolAddress(&p_xt, g_xt);
    cudaGetSymbolAddress(&p_kt, g_kt);
    cudaGetSymbolAddress(&p_vth, g_vth);
    float* scores = (float*)p_scores;
    __half* attn = (__half*)p_attn;
    float* xt = (float*)p_xt;
    float* kt = (float*)p_kt;
    __half* vth = (__half*)p_vth;

    // Pre-convert inputs (one fused launch); transpose+fp16-convert V.
    cvt_inputs<<<(unsigned)((NX + NK) / 1024), 256>>>(x, Kw, xt, kt);
    transpose_v<<<dim3(E_DIM / 32, P_DIM / 32), dim3(32, 8)>>>(V);

    // raw scores = x @ K^T (tf32; scale folded into softmax)
    gemm_tc<<<dim3(P_DIM / BN, M_TOTAL / BM), 256, SMEM_BYTES>>>(
        xt, kt, scores, E_DIM / KC32, E_DIM, E_DIM, P_DIM);

    softmax_rows<<<M_TOTAL, 256>>>(0.03125f);

    // out = attn @ V (fp16 inputs, fp32 accumulate; B = V^T, K-major over P)
    gemm_hc<<<dim3(E_DIM / BN, M_TOTAL / BM), 256, SMEM_BYTES>>>(
        attn, vth, out, P_DIM / KC64, P_DIM, P_DIM, E_DIM);
}

// round 14
// speedup vs baseline: 4.6275x; 1.3749x over previous
#include <cuda_runtime.h>
#include <cuda_fp16.h>
#include <stdint.h>

// ---------------------------------------------------------------------------
// Problem dims (fixed by the dataset)
// ---------------------------------------------------------------------------
#define M_TOTAL 8192   // B*S = 4*2048
#define E_DIM   1024
#define P_DIM   4096

// Device scratch (__device__ globals = sanctioned scratch)
__device__ float  g_scores[(size_t)M_TOTAL * (size_t)P_DIM]; // 128 MB fp32 scores
__device__ __half g_attn[(size_t)M_TOTAL * (size_t)P_DIM];   // 64 MB fp16 attn
__device__ __half g_xh[(size_t)M_TOTAL * (size_t)E_DIM];     // 16 MB fp16(x)
__device__ __half g_kh[(size_t)P_DIM * (size_t)E_DIM];       // 8 MB fp16(K)
__device__ __half g_vth[(size_t)E_DIM * (size_t)P_DIM];      // 8 MB fp16(V^T)

// ---------------------------------------------------------------------------
// Helpers
// ---------------------------------------------------------------------------
__device__ __forceinline__ uint32_t smem_u32(const void* p) {
    uint32_t a;
    asm("{ .reg .u64 t; cvta.to.shared.u64 t, %1; cvt.u32.u64 %0, t; }"
        : "=r"(a) : "l"(p));
    return a;
}

__device__ __forceinline__ void cp_async16(uint32_t dst, const void* src) {
    asm volatile("cp.async.cg.shared.global [%0], [%1], 16;"
                 :: "r"(dst), "l"(src) : "memory");
}
#define CP_ASYNC_COMMIT() asm volatile("cp.async.commit_group;" ::: "memory")
#define CP_ASYNC_WAIT_1() asm volatile("cp.async.wait_group 1;" ::: "memory")

__device__ __forceinline__ void ldsm_x4(uint32_t r[4], uint32_t addr) {
    asm volatile("ldmatrix.sync.aligned.m8n8.x4.shared.b16 {%0,%1,%2,%3}, [%4];"
                 : "=r"(r[0]), "=r"(r[1]), "=r"(r[2]), "=r"(r[3]) : "r"(addr));
}

__device__ __forceinline__ void mma_f16(float c[4], const uint32_t a[4], const uint32_t b[2]) {
    asm volatile(
        "mma.sync.aligned.m16n8k16.row.col.f32.f16.f16.f32 "
        "{%0,%1,%2,%3}, {%4,%5,%6,%7}, {%8,%9}, {%0,%1,%2,%3};"
        : "+f"(c[0]), "+f"(c[1]), "+f"(c[2]), "+f"(c[3])
        : "r"(a[0]), "r"(a[1]), "r"(a[2]), "r"(a[3]),
          "r"(b[0]), "r"(b[1]));
}

// ---------------------------------------------------------------------------
// FP16 GEMM (fp32 accum): D[m,n] = sum_k A[m,k]*B[n,k], both K-major fp16.
// CTA 128x128, KC=64 halves (128-byte rows), 256 thr (8 warps 2x4), warp
// tile 64x32, mma m16n8k16, 3-stage cp.async, 2 CTAs/SM (96KB smem each).
//
// XOR swizzle in 128-byte rows over 16B groups:
//   byte(r, g) -> r*128 + ((g ^ (r&7)) << 4)
// cp.async 16B stores and every ldmatrix phase (8 rows, distinct r&7) are
// bank-conflict-free.
//
// A fragments: ldmatrix.x4 per mi (2 row-blocks x 2 k-halves).
// B fragments: ldmatrix.x4 PAIRED (one x4 = two adjacent ni tiles:
// lanes 0-15 -> tile 2np, lanes 16-31 -> tile 2np+1).
// Next stage's cp.asyncs issued between kk=0 and kk=1 (post-barrier critical
// path stays LDSM-only).
// ---------------------------------------------------------------------------
#define BM 128
#define BN 128
#define KC64 64
#define STAGES 3
#define STG_WORDS 8192                        // 32KB per stage (A 16KB + B 16KB)
#define SMEM_BYTES (STAGES * STG_WORDS * 4)   // 98304 per CTA

__global__ __launch_bounds__(256, 2) void gemm_hc(const __half* __restrict__ Ag,
                                                  const __half* __restrict__ Bg,
                                                  float* __restrict__ Dg,
                                                  int nk, int lda, int ldb, int ldd) {
    extern __shared__ uint32_t sm[];
    const uint32_t sbase = smem_u32(sm);
    const int tid  = threadIdx.x;
    const int lane = tid & 31;
    const int wid  = tid >> 5;
    const int wm   = (wid >> 2) * 64;
    const int wn   = (wid & 3) * 32;
    const int bm   = blockIdx.y * BM;
    const int bn   = blockIdx.x * BN;
    const int tig  = lane & 3;
    const int grp  = lane >> 2;

    const int gflA = lane >> 4;          // k-half flag for A (matrices 2,3)
    uint32_t preA[4]; int rb7A[4];
    #pragma unroll
    for (int mi = 0; mi < 4; mi++) {
        int r = wm + mi * 16 + (lane & 15);
        preA[mi] = (uint32_t)(r * 128);
        rb7A[mi] = r & 7;
    }
    const int gflB = (lane >> 3) & 1;    // k-half flag for B
    uint32_t preB[2]; int rb7B[2];
    #pragma unroll
    for (int np = 0; np < 2; np++) {
        int r = wn + np * 16 + ((lane >> 4) << 3) + (lane & 7);
        preB[np] = (uint32_t)(r * 128);
        rb7B[np] = r & 7;
    }

    // A: 128 rows x 128B -> 1024 16B-chunks -> 4/thread; B same.
    auto issue_stage = [&](int stage, int k0) {
        const uint32_t abase = sbase + (uint32_t)stage * (STG_WORDS * 4);
        const uint32_t bbase = abase + 4096 * 4;
        #pragma unroll
        for (int i = 0; i < 4; i++) {
            int lin = tid + 256 * i;
            int r   = lin >> 3;
            int g   = lin & 7;
            uint32_t boff = (uint32_t)(r * 128 + ((g ^ (r & 7)) << 4));
            cp_async16(abase + boff, Ag + (size_t)(bm + r) * lda + k0 + g * 8);
        }
        #pragma unroll
        for (int i = 0; i < 4; i++) {
            int lin = tid + 256 * i;
            int r   = lin >> 3;
            int g   = lin & 7;
            uint32_t boff = (uint32_t)(r * 128 + ((g ^ (r & 7)) << 4));
            cp_async16(bbase + boff, Bg + (size_t)(bn + r) * ldb + k0 + g * 8);
        }
    };

    float acc[4][4][4];
    #pragma unroll
    for (int mi = 0; mi < 4; mi++)
        #pragma unroll
        for (int ni = 0; ni < 4; ni++)
            #pragma unroll
            for (int c = 0; c < 4; c++)
                acc[mi][ni][c] = 0.0f;

    issue_stage(0, 0);
    CP_ASYNC_COMMIT();
    issue_stage(1, KC64);
    CP_ASYNC_COMMIT();

    int stage_rd = 0;
    int stage_wr = 2;
    for (int k = 0; k < nk; k++) {
        CP_ASYNC_WAIT_1();
        __syncthreads();

        const uint32_t astage = sbase + (uint32_t)stage_rd * (STG_WORDS * 4);
        const uint32_t bstage = astage + 4096 * 4;

        #pragma unroll
        for (int kk = 0; kk < 4; kk++) {   // 4 x k16 steps over KC64
            uint32_t a[4][4];
            #pragma unroll
            for (int mi = 0; mi < 4; mi++) {
                uint32_t addr = astage + preA[mi] +
                                (uint32_t)((((2 * kk + gflA) ^ rb7A[mi])) << 4);
                ldsm_x4(a[mi], addr);
            }
            uint32_t b[4][2];
            {
                uint32_t b4[4];
                uint32_t addr0 = bstage + preB[0] +
                                 (uint32_t)((((2 * kk + gflB) ^ rb7B[0])) << 4);
                ldsm_x4(b4, addr0);
                b[0][0] = b4[0]; b[0][1] = b4[1];
                b[1][0] = b4[2]; b[1][1] = b4[3];
            }
            #pragma unroll
            for (int mi = 0; mi < 4; mi++) {
                mma_f16(acc[mi][0], a[mi], b[0]);
                mma_f16(acc[mi][1], a[mi], b[1]);
            }
            {
                uint32_t b4[4];
                uint32_t addr1 = bstage + preB[1] +
                                 (uint32_t)((((2 * kk + gflB) ^ rb7B[1])) << 4);
                ldsm_x4(b4, addr1);
                b[2][0] = b4[0]; b[2][1] = b4[1];
                b[3][0] = b4[2]; b[3][1] = b4[3];
            }
            #pragma unroll
            for (int mi = 0; mi < 4; mi++) {
                mma_f16(acc[mi][2], a[mi], b[2]);
                mma_f16(acc[mi][3], a[mi], b[3]);
            }
            if (kk == 0) {
                if (k + STAGES - 1 < nk)
                    issue_stage(stage_wr, (k + STAGES - 1) * KC64);
                CP_ASYNC_COMMIT();
            }
        }

        stage_rd = (stage_rd + 1 == STAGES) ? 0 : stage_rd + 1;
        stage_wr = (stage_wr + 1 == STAGES) ? 0 : stage_wr + 1;
    }

    #pragma unroll
    for (int mi = 0; mi < 4; mi++) {
        #pragma unroll
        for (int ni = 0; ni < 4; ni++) {
            const int r = bm + wm + mi * 16 + grp;
            const int c = bn + wn + ni * 8 + 2 * tig;
            float2 v0 = make_float2(acc[mi][ni][0], acc[mi][ni][1]);
            float2 v1 = make_float2(acc[mi][ni][2], acc[mi][ni][3]);
            *(float2*)&Dg[(size_t)r       * ldd + c] = v0;
            *(float2*)&Dg[(size_t)(r + 8) * ldd + c] = v1;
        }
    }
}

// ---------------------------------------------------------------------------
// Elementwise fp16 convert for x and K in ONE launch (8 floats/thread).
// ---------------------------------------------------------------------------
#define NX ((size_t)M_TOTAL * E_DIM)
#define NK ((size_t)P_DIM * E_DIM)
__global__ __launch_bounds__(256) void cvt_inputs(const float* __restrict__ x,
                                                  const float* __restrict__ Kw,
                                                  __half* __restrict__ xh,
                                                  __half* __restrict__ kh) {
    const size_t i = ((size_t)blockIdx.x * 256 + threadIdx.x) * 8;
    const float* src;
    __half* dst;
    size_t off;
    if (i < NX) { src = x;  dst = xh; off = i; }
    else        { src = Kw; dst = kh; off = i - NX; }
    float4 v0 = *(const float4*)(src + off);
    float4 v1 = *(const float4*)(src + off + 4);
    __half2 h0 = __floats2half2_rn(v0.x, v0.y);
    __half2 h1 = __floats2half2_rn(v0.z, v0.w);
    __half2 h2 = __floats2half2_rn(v1.x, v1.y);
    __half2 h3 = __floats2half2_rn(v1.z, v1.w);
    uint4 w;
    w.x = *(uint32_t*)&h0; w.y = *(uint32_t*)&h1;
    w.z = *(uint32_t*)&h2; w.w = *(uint32_t*)&h3;
    *(uint4*)(dst + off) = w;
}

// ---------------------------------------------------------------------------
// V transpose + fp16 convert: g_vth[e][p] = fp16(V[p][e])
// ---------------------------------------------------------------------------
__global__ __launch_bounds__(256) void transpose_v(const float* __restrict__ V) {
    __shared__ float t[32][33];
    const int bx = blockIdx.x * 32;  // E
    const int by = blockIdx.y * 32;  // P
    const int tx = threadIdx.x;
    const int ty = threadIdx.y;
    #pragma unroll
    for (int j = 0; j < 32; j += 8)
        t[ty + j][tx] = V[(size_t)(by + ty + j) * E_DIM + bx + tx];
    __syncthreads();
    #pragma unroll
    for (int j = 0; j < 32; j += 8)
        g_vth[(size_t)(bx + ty + j) * P_DIM + by + tx] =
            __float2half_rn(t[tx][ty + j]);
}

// ---------------------------------------------------------------------------
// Row softmax over P_DIM=4096: reads fp32 scores, writes fp16 attn.
// 1/sqrt(E) scale folded in.
// ---------------------------------------------------------------------------
__global__ __launch_bounds__(256) void softmax_rows(float scale) {
    __shared__ float red[8];
    const int t    = threadIdx.x;
    const int lane = t & 31;
    const int w    = t >> 5;
    const float4* sr = (const float4*)(g_scores + (size_t)blockIdx.x * P_DIM);
    uint2* ah = (uint2*)(g_attn + (size_t)blockIdx.x * P_DIM);

    float4 v[4];
    float m = -3.0e38f;
    #pragma unroll
    for (int j = 0; j < 4; j++) {
        v[j] = sr[t + 256 * j];
        m = fmaxf(m, fmaxf(fmaxf(v[j].x, v[j].y), fmaxf(v[j].z, v[j].w)));
    }
    #pragma unroll
    for (int o = 16; o > 0; o >>= 1)
        m = fmaxf(m, __shfl_xor_sync(0xffffffffu, m, o));
    if (lane == 0) red[w] = m;
    __syncthreads();
    m = red[0];
    #pragma unroll
    for (int i = 1; i < 8; i++) m = fmaxf(m, red[i]);

    float s = 0.0f;
    #pragma unroll
    for (int j = 0; j < 4; j++) {
        v[j].x = __expf((v[j].x - m) * scale);
        v[j].y = __expf((v[j].y - m) * scale);
        v[j].z = __expf((v[j].z - m) * scale);
        v[j].w = __expf((v[j].w - m) * scale);
        s += v[j].x + v[j].y + v[j].z + v[j].w;
    }
    #pragma unroll
    for (int o = 16; o > 0; o >>= 1)
        s += __shfl_xor_sync(0xffffffffu, s, o);
    __syncthreads();
    if (lane == 0) red[w] = s;
    __syncthreads();
    s = 0.0f;
    #pragma unroll
    for (int i = 0; i < 8; i++) s += red[i];
    const float inv = 1.0f / s;

    #pragma unroll
    for (int j = 0; j < 4; j++) {
        __half2 lo = __floats2half2_rn(v[j].x * inv, v[j].y * inv);
        __half2 hi = __floats2half2_rn(v[j].z * inv, v[j].w * inv);
        uint2 o;
        o.x = *(uint32_t*)&lo;
        o.y = *(uint32_t*)&hi;
        ah[t + 256 * j] = o;
    }
}

// ---------------------------------------------------------------------------
// Launch. Inputs: x [4,2048,1024], K [4096,1024], V [4096,1024]; out fp32.
// Only kernel launches enqueued -> graph-capturable.
// ---------------------------------------------------------------------------
extern "C" void kernel_launch(void* const* d_in, const int* in_sizes, int n_in,
                              void* d_out, int out_size) {
    (void)in_sizes; (void)n_in; (void)out_size;
    const float* x  = (const float*)d_in[0];
    const float* Kw = (const float*)d_in[1];
    const float* V  = (const float*)d_in[2];
    float* out = (float*)d_out;

    cudaFuncSetAttribute(gemm_hc, cudaFuncAttributeMaxDynamicSharedMemorySize,
                         SMEM_BYTES);

    void *p_scores, *p_attn, *p_xh, *p_kh, *p_vth;
    cudaGetSymbolAddress(&p_scores, g_scores);
    cudaGetSymbolAddress(&p_attn, g_attn);
    cudaGetSymbolAddress(&p_xh, g_xh);
    cudaGetSymbolAddress(&p_kh, g_kh);
    cudaGetSymbolAddress(&p_vth, g_vth);
    float* scores = (float*)p_scores;
    __half* attn = (__half*)p_attn;
    __half* xh = (__half*)p_xh;
    __half* kh = (__half*)p_kh;
    __half* vth = (__half*)p_vth;

    // Pre-convert x,K to fp16 (one fused launch); transpose+fp16-convert V.
    cvt_inputs<<<(unsigned)((NX + NK) / 2048), 256>>>(x, Kw, xh, kh);
    transpose_v<<<dim3(E_DIM / 32, P_DIM / 32), dim3(32, 8)>>>(V);

    // raw scores = x @ K^T (fp16 in, fp32 accum; scale folded into softmax)
    gemm_hc<<<dim3(P_DIM / BN, M_TOTAL / BM), 256, SMEM_BYTES>>>(
        xh, kh, scores, E_DIM / KC64, E_DIM, E_DIM, P_DIM);

    softmax_rows<<<M_TOTAL, 256>>>(0.03125f);

    // out = attn @ V (fp16 in, fp32 accum; B = V^T, K-major over P)
    gemm_hc<<<dim3(E_DIM / BN, M_TOTAL / BM), 256, SMEM_BYTES>>>(
        attn, vth, out, P_DIM / KC64, P_DIM, P_DIM, E_DIM);
}